// round 1
// baseline (speedup 1.0000x reference)
#include <cuda_runtime.h>
#include <cuda_bf16.h>
#include <math.h>

#define N_NODES 100000
#define N_EDGES 1600000
#define F_IN 256
#define HID 256
#define NC 40

// ---------------- scratch (static device globals; no allocation) ----------------
__device__ float g_dis[N_NODES];                       // deg -> deg^{-1/2}
__device__ float g_h1[(size_t)N_NODES * HID];          // x @ W1 + b1
__device__ float g_a1[(size_t)N_NODES * HID];          // aggregated layer 1
__device__ float g_h2[(size_t)N_NODES * NC];           // relu(a1) @ W2 + b2
__device__ float g_a2[(size_t)N_NODES * NC];           // aggregated layer 2

// ---------------- degree ----------------
__global__ void k_deg_init() {
    int i = blockIdx.x * blockDim.x + threadIdx.x;
    if (i < N_NODES) g_dis[i] = 1.0f;  // self-loop weight
}

__global__ void k_deg_edges(const int* __restrict__ dst, const float* __restrict__ ew) {
    int e = blockIdx.x * blockDim.x + threadIdx.x;
    if (e < N_EDGES) atomicAdd(&g_dis[dst[e]], ew[e]);
}

__global__ void k_deg_fin() {
    int i = blockIdx.x * blockDim.x + threadIdx.x;
    if (i < N_NODES) g_dis[i] = rsqrtf(g_dis[i]);  // deg >= 1 always
}

// ---------------- GEMM1: g_h1 = x @ W1 + b1   (M=100000, K=256, N=256) ----------------
// 128x128 block tile, BK=16, 256 threads, 8x8 microtile
__global__ __launch_bounds__(256) void k_gemm1(const float* __restrict__ A,
                                               const float* __restrict__ B,
                                               const float* __restrict__ bias) {
    __shared__ float As[16][128];
    __shared__ float Bs[16][128];

    const int tid = threadIdx.x;
    const int tx = tid % 16;         // N direction
    const int ty = tid / 16;         // M direction
    const int rowBase = blockIdx.x * 128;
    const int colBase = blockIdx.y * 128;

    float acc[8][8];
#pragma unroll
    for (int i = 0; i < 8; i++)
#pragma unroll
        for (int j = 0; j < 8; j++) acc[i][j] = 0.0f;

    for (int k0 = 0; k0 < 256; k0 += 16) {
        // load A tile: 128 rows x 16 k, store transposed
#pragma unroll
        for (int l = 0; l < 2; l++) {
            int idx = tid + l * 256;         // float4 index 0..511
            int r = idx >> 2;                // 0..127
            int c4 = idx & 3;                // 0..3
            float4 v = make_float4(0.f, 0.f, 0.f, 0.f);
            int gr = rowBase + r;
            if (gr < N_NODES)
                v = *(const float4*)(A + (size_t)gr * 256 + k0 + c4 * 4);
            As[c4 * 4 + 0][r] = v.x;
            As[c4 * 4 + 1][r] = v.y;
            As[c4 * 4 + 2][r] = v.z;
            As[c4 * 4 + 3][r] = v.w;
        }
        // load B tile: 16 k x 128 cols
#pragma unroll
        for (int l = 0; l < 2; l++) {
            int idx = tid + l * 256;
            int r = idx >> 5;                // 0..15
            int c4 = idx & 31;               // 0..31
            float4 v = *(const float4*)(B + (size_t)(k0 + r) * 256 + colBase + c4 * 4);
            *(float4*)&Bs[r][c4 * 4] = v;
        }
        __syncthreads();

#pragma unroll
        for (int k = 0; k < 16; k++) {
            float ar[8], br[8];
#pragma unroll
            for (int i = 0; i < 8; i++) ar[i] = As[k][ty * 8 + i];
#pragma unroll
            for (int j = 0; j < 8; j++) br[j] = Bs[k][tx * 8 + j];
#pragma unroll
            for (int i = 0; i < 8; i++)
#pragma unroll
                for (int j = 0; j < 8; j++) acc[i][j] = fmaf(ar[i], br[j], acc[i][j]);
        }
        __syncthreads();
    }

#pragma unroll
    for (int i = 0; i < 8; i++) {
        int gr = rowBase + ty * 8 + i;
        if (gr < N_NODES) {
#pragma unroll
            for (int j = 0; j < 8; j++) {
                int gc = colBase + tx * 8 + j;
                g_h1[(size_t)gr * 256 + gc] = acc[i][j] + bias[gc];
            }
        }
    }
}

// ---------------- self-loop init: a1 = h1 * dis^2 ----------------
__global__ void k_selfloop1() {
    int idx = blockIdx.x * blockDim.x + threadIdx.x;  // float4 index
    const int total = N_NODES * (HID / 4);
    if (idx >= total) return;
    int node = idx / (HID / 4);
    float d = g_dis[node];
    float s = d * d;
    float4 v = ((const float4*)g_h1)[idx];
    v.x *= s; v.y *= s; v.z *= s; v.w *= s;
    ((float4*)g_a1)[idx] = v;
}

// ---------------- edge aggregation layer 1: one warp per edge ----------------
__global__ __launch_bounds__(256) void k_agg1(const int* __restrict__ src,
                                              const int* __restrict__ dst,
                                              const float* __restrict__ ew) {
    int e = blockIdx.x * 8 + (threadIdx.x >> 5);
    if (e >= N_EDGES) return;
    int lane = threadIdx.x & 31;
    int s = __ldg(&src[e]);
    int d = __ldg(&dst[e]);
    float norm = g_dis[s] * __ldg(&ew[e]) * g_dis[d];
    const float4* hrow = (const float4*)(g_h1 + (size_t)s * HID);
    float4* arow = (float4*)(g_a1 + (size_t)d * HID);
#pragma unroll
    for (int j = 0; j < 2; j++) {
        int off = lane + j * 32;  // float4 index 0..63
        float4 v = hrow[off];
        v.x *= norm; v.y *= norm; v.z *= norm; v.w *= norm;
        atomicAdd(&arow[off], v);  // sm_90+ vector red.global.add.v4.f32
    }
}

// ---------------- GEMM2: g_h2 = relu(a1) @ W2 + b2  (K=256, N=40) ----------------
__global__ __launch_bounds__(256) void k_gemm2(const float* __restrict__ W2,
                                               const float* __restrict__ b2) {
    __shared__ float sW[HID * NC];  // 40 KB
    for (int i = threadIdx.x; i < HID * NC; i += 256) sW[i] = W2[i];
    __syncthreads();

    int row = blockIdx.x * 64 + (threadIdx.x >> 2);
    int cg = (threadIdx.x & 3) * 10;
    if (row >= N_NODES) return;

    float acc[10];
#pragma unroll
    for (int c = 0; c < 10; c++) acc[c] = b2[cg + c];

    const float4* a = (const float4*)(g_a1 + (size_t)row * HID);
    for (int k4 = 0; k4 < HID / 4; k4++) {
        float4 av = a[k4];
        float v[4] = {fmaxf(av.x, 0.f), fmaxf(av.y, 0.f), fmaxf(av.z, 0.f), fmaxf(av.w, 0.f)};
#pragma unroll
        for (int kk = 0; kk < 4; kk++) {
            int k = k4 * 4 + kk;
#pragma unroll
            for (int c = 0; c < 10; c++)
                acc[c] = fmaf(v[kk], sW[k * NC + cg + c], acc[c]);
        }
    }
#pragma unroll
    for (int c = 0; c < 10; c++) g_h2[(size_t)row * NC + cg + c] = acc[c];
}

// ---------------- self-loop init layer 2 ----------------
__global__ void k_selfloop2() {
    int idx = blockIdx.x * blockDim.x + threadIdx.x;  // float4 index
    const int total = N_NODES * (NC / 4);
    if (idx >= total) return;
    int node = idx / (NC / 4);
    float d = g_dis[node];
    float s = d * d;
    float4 v = ((const float4*)g_h2)[idx];
    v.x *= s; v.y *= s; v.z *= s; v.w *= s;
    ((float4*)g_a2)[idx] = v;
}

// ---------------- edge aggregation layer 2: thread per (edge, quad) ----------------
__global__ __launch_bounds__(256) void k_agg2(const int* __restrict__ src,
                                              const int* __restrict__ dst,
                                              const float* __restrict__ ew) {
    int t = blockIdx.x * blockDim.x + threadIdx.x;
    const int total = N_EDGES * 10;  // 10 float4s per edge
    if (t >= total) return;
    int e = t / 10;
    int q = t - e * 10;
    int s = __ldg(&src[e]);
    int d = __ldg(&dst[e]);
    float norm = g_dis[s] * __ldg(&ew[e]) * g_dis[d];
    float4 v = *(const float4*)(g_h2 + (size_t)s * NC + q * 4);
    v.x *= norm; v.y *= norm; v.z *= norm; v.w *= norm;
    atomicAdd((float4*)(g_a2 + (size_t)d * NC + q * 4), v);
}

// ---------------- log_softmax: one warp per row ----------------
__global__ __launch_bounds__(256) void k_lsm(float* __restrict__ out) {
    int row = blockIdx.x * 8 + (threadIdx.x >> 5);
    if (row >= N_NODES) return;
    int lane = threadIdx.x & 31;
    const float* a = g_a2 + (size_t)row * NC;
    float v1 = (lane < NC) ? a[lane] : -INFINITY;
    float v2 = (lane + 32 < NC) ? a[lane + 32] : -INFINITY;
    float m = fmaxf(v1, v2);
#pragma unroll
    for (int off = 16; off >= 1; off >>= 1)
        m = fmaxf(m, __shfl_xor_sync(0xFFFFFFFFu, m, off));
    float s = 0.f;
    if (lane < NC) s += __expf(v1 - m);
    if (lane + 32 < NC) s += __expf(v2 - m);
#pragma unroll
    for (int off = 16; off >= 1; off >>= 1)
        s += __shfl_xor_sync(0xFFFFFFFFu, s, off);
    float ls = m + logf(s);
    if (lane < NC) out[(size_t)row * NC + lane] = v1 - ls;
    if (lane + 32 < NC) out[(size_t)row * NC + lane + 32] = v2 - ls;
}

// ---------------- launch ----------------
extern "C" void kernel_launch(void* const* d_in, const int* in_sizes, int n_in,
                              void* d_out, int out_size) {
    const float* x  = (const float*)d_in[0];
    const int*   ei = (const int*)d_in[1];
    const float* ew = (const float*)d_in[2];
    const float* W1 = (const float*)d_in[3];
    const float* b1 = (const float*)d_in[4];
    const float* W2 = (const float*)d_in[5];
    const float* b2 = (const float*)d_in[6];
    float* out = (float*)d_out;

    const int* src = ei;
    const int* dst = ei + N_EDGES;

    k_deg_init<<<(N_NODES + 255) / 256, 256>>>();
    k_deg_edges<<<(N_EDGES + 255) / 256, 256>>>(dst, ew);
    k_deg_fin<<<(N_NODES + 255) / 256, 256>>>();

    k_gemm1<<<dim3((N_NODES + 127) / 128, 2), 256>>>(x, W1, b1);

    k_selfloop1<<<(N_NODES * (HID / 4) + 255) / 256, 256>>>();
    k_agg1<<<(N_EDGES + 7) / 8, 256>>>(src, dst, ew);

    k_gemm2<<<(N_NODES + 63) / 64, 256>>>(W2, b2);

    k_selfloop2<<<(N_NODES * (NC / 4) + 255) / 256, 256>>>();
    k_agg2<<<(N_EDGES * 10 + 255) / 256, 256>>>(src, dst, ew);

    k_lsm<<<(N_NODES + 7) / 8, 256>>>(out);
}

// round 3
// speedup vs baseline: 1.2712x; 1.2712x over previous
#include <cuda_runtime.h>
#include <math.h>

#define N_NODES 100000
#define N_EDGES 1600000
#define F_IN 256
#define HID 256
#define NC 40

// ---------------- scratch (static device globals; no allocation) ----------------
__device__ float g_dis[N_NODES];                  // deg -> deg^{-1/2}
__device__ int   g_cnt[N_NODES];                  // incoming-edge counts
__device__ int   g_off[N_NODES + 1];              // CSR offsets (by dst)
__device__ int   g_cur[N_NODES];                  // fill cursors
__device__ int   g_ssrc[N_EDGES];                 // src sorted by dst
__device__ float g_snorm[N_EDGES];                // norm sorted by dst
__device__ float g_h1[(size_t)N_NODES * HID];     // x @ W1 + b1
__device__ float g_a1[(size_t)N_NODES * HID];     // relu(aggregated layer 1)
__device__ float g_h2[(size_t)N_NODES * NC];      // a1 @ W2 + b2

// ---------------- init: deg=1 (self loop), counters=0 ----------------
__global__ void k_init() {
    int i = blockIdx.x * blockDim.x + threadIdx.x;
    if (i < N_NODES) { g_dis[i] = 1.0f; g_cnt[i] = 0; g_cur[i] = 0; }
}

__global__ void k_cnt(const int* __restrict__ dst, const float* __restrict__ ew) {
    int e = blockIdx.x * blockDim.x + threadIdx.x;
    if (e < N_EDGES) {
        int d = dst[e];
        atomicAdd(&g_dis[d], ew[e]);
        atomicAdd(&g_cnt[d], 1);
    }
}

__global__ void k_fin() {
    int i = blockIdx.x * blockDim.x + threadIdx.x;
    if (i < N_NODES) g_dis[i] = rsqrtf(g_dis[i]);  // deg >= 1 always
}

// ---------------- single-block exclusive scan of g_cnt -> g_off ----------------
__global__ __launch_bounds__(1024) void k_scan() {
    __shared__ int s[1024];
    const int C = (N_NODES + 1023) / 1024;  // 98
    int t = threadIdx.x;
    int beg = t * C;
    int end = beg + C; if (end > N_NODES) end = N_NODES;
    int sum = 0;
    for (int i = beg; i < end; i++) sum += g_cnt[i];
    s[t] = sum;
    __syncthreads();
    for (int o = 1; o < 1024; o <<= 1) {
        int u = (t >= o) ? s[t - o] : 0;
        __syncthreads();
        s[t] += u;
        __syncthreads();
    }
    int base = s[t] - sum;
    int run = base;
    for (int i = beg; i < end; i++) { g_off[i] = run; run += g_cnt[i]; }
    if (t == 1023) g_off[N_NODES] = s[1023];
}

// ---------------- fill CSR with (src, norm) ----------------
__global__ void k_fill(const int* __restrict__ src, const int* __restrict__ dst,
                       const float* __restrict__ ew) {
    int e = blockIdx.x * blockDim.x + threadIdx.x;
    if (e >= N_EDGES) return;
    int d = dst[e];
    int s = src[e];
    int pos = g_off[d] + atomicAdd(&g_cur[d], 1);
    g_ssrc[pos] = s;
    g_snorm[pos] = g_dis[s] * ew[e] * g_dis[d];
}

// ---------------- GEMM1: g_h1 = x @ W1 + b1   (M=100000, K=256, N=256) ----------------
__global__ __launch_bounds__(256) void k_gemm1(const float* __restrict__ A,
                                               const float* __restrict__ B,
                                               const float* __restrict__ bias) {
    __shared__ float As[16][128];
    __shared__ float Bs[16][128];

    const int tid = threadIdx.x;
    const int tx = tid % 16;
    const int ty = tid / 16;
    const int rowBase = blockIdx.x * 128;
    const int colBase = blockIdx.y * 128;

    float acc[8][8];
#pragma unroll
    for (int i = 0; i < 8; i++)
#pragma unroll
        for (int j = 0; j < 8; j++) acc[i][j] = 0.0f;

    for (int k0 = 0; k0 < 256; k0 += 16) {
#pragma unroll
        for (int l = 0; l < 2; l++) {
            int idx = tid + l * 256;
            int r = idx >> 2;
            int c4 = idx & 3;
            float4 v = make_float4(0.f, 0.f, 0.f, 0.f);
            int gr = rowBase + r;
            if (gr < N_NODES)
                v = *(const float4*)(A + (size_t)gr * 256 + k0 + c4 * 4);
            As[c4 * 4 + 0][r] = v.x;
            As[c4 * 4 + 1][r] = v.y;
            As[c4 * 4 + 2][r] = v.z;
            As[c4 * 4 + 3][r] = v.w;
        }
#pragma unroll
        for (int l = 0; l < 2; l++) {
            int idx = tid + l * 256;
            int r = idx >> 5;
            int c4 = idx & 31;
            float4 v = *(const float4*)(B + (size_t)(k0 + r) * 256 + colBase + c4 * 4);
            *(float4*)&Bs[r][c4 * 4] = v;
        }
        __syncthreads();

#pragma unroll
        for (int k = 0; k < 16; k++) {
            float ar[8], br[8];
#pragma unroll
            for (int i = 0; i < 8; i++) ar[i] = As[k][ty * 8 + i];
#pragma unroll
            for (int j = 0; j < 8; j++) br[j] = Bs[k][tx * 8 + j];
#pragma unroll
            for (int i = 0; i < 8; i++)
#pragma unroll
                for (int j = 0; j < 8; j++) acc[i][j] = fmaf(ar[i], br[j], acc[i][j]);
        }
        __syncthreads();
    }

#pragma unroll
    for (int i = 0; i < 8; i++) {
        int gr = rowBase + ty * 8 + i;
        if (gr < N_NODES) {
#pragma unroll
            for (int j = 0; j < 8; j++) {
                int gc = colBase + tx * 8 + j;
                g_h1[(size_t)gr * 256 + gc] = acc[i][j] + bias[gc];
            }
        }
    }
}

// ---------------- agg1: 2 warps per dst node (128 features each), CSR gather, relu ----------------
__global__ __launch_bounds__(256) void k_agg1() {
    int wid = blockIdx.x * 8 + (threadIdx.x >> 5);   // global warp id
    int node = wid >> 1;
    if (node >= N_NODES) return;
    int half = wid & 1;                               // 0: feats 0..127, 1: 128..255
    int lane = threadIdx.x & 31;
    int fo = half * 32 + lane;                        // float4 index within row (0..63)

    float dv = g_dis[node];
    float self = dv * dv;
    float4 acc = ((const float4*)(g_h1 + (size_t)node * HID))[fo];
    acc.x *= self; acc.y *= self; acc.z *= self; acc.w *= self;

    int beg = g_off[node], end = g_off[node + 1];
    for (int p = beg; p < end; p++) {
        int s = __ldg(&g_ssrc[p]);       // warp-uniform broadcast
        float nm = __ldg(&g_snorm[p]);
        float4 v = ((const float4*)(g_h1 + (size_t)s * HID))[fo];
        acc.x = fmaf(v.x, nm, acc.x);
        acc.y = fmaf(v.y, nm, acc.y);
        acc.z = fmaf(v.z, nm, acc.z);
        acc.w = fmaf(v.w, nm, acc.w);
    }

    acc.x = fmaxf(acc.x, 0.f); acc.y = fmaxf(acc.y, 0.f);
    acc.z = fmaxf(acc.z, 0.f); acc.w = fmaxf(acc.w, 0.f);
    ((float4*)(g_a1 + (size_t)node * HID))[fo] = acc;
}

// ---------------- GEMM2: g_h2 = a1 @ W2 + b2  (a1 already relu'd) ----------------
__global__ __launch_bounds__(256) void k_gemm2(const float* __restrict__ W2,
                                               const float* __restrict__ b2) {
    __shared__ float sW[HID * NC];  // 40 KB
    for (int i = threadIdx.x; i < HID * NC; i += 256) sW[i] = W2[i];
    __syncthreads();

    int row = blockIdx.x * 64 + (threadIdx.x >> 2);
    int cg = (threadIdx.x & 3) * 10;
    if (row >= N_NODES) return;

    float acc[10];
#pragma unroll
    for (int c = 0; c < 10; c++) acc[c] = b2[cg + c];

    const float4* a = (const float4*)(g_a1 + (size_t)row * HID);
    for (int k4 = 0; k4 < HID / 4; k4++) {
        float4 av = a[k4];
        float v[4] = {av.x, av.y, av.z, av.w};
#pragma unroll
        for (int kk = 0; kk < 4; kk++) {
            int k = k4 * 4 + kk;
#pragma unroll
            for (int c = 0; c < 10; c++)
                acc[c] = fmaf(v[kk], sW[k * NC + cg + c], acc[c]);
        }
    }
#pragma unroll
    for (int c = 0; c < 10; c++) g_h2[(size_t)row * NC + cg + c] = acc[c];
}

// ---------------- agg2 + log_softmax fused: warp per dst node ----------------
__global__ __launch_bounds__(256) void k_agg2_lsm(float* __restrict__ out) {
    int node = blockIdx.x * 8 + (threadIdx.x >> 5);
    if (node >= N_NODES) return;
    int lane = threadIdx.x & 31;

    float dv = g_dis[node];
    float self = dv * dv;
    const float* hd = g_h2 + (size_t)node * NC;
    float a0 = hd[lane] * self;                          // classes 0..31
    float a1 = (lane < 8) ? hd[lane + 32] * self : 0.f;  // classes 32..39

    int beg = g_off[node], end = g_off[node + 1];
    for (int p = beg; p < end; p++) {
        int s = __ldg(&g_ssrc[p]);
        float nm = __ldg(&g_snorm[p]);
        const float* hs = g_h2 + (size_t)s * NC;
        a0 = fmaf(__ldg(&hs[lane]), nm, a0);
        if (lane < 8) a1 = fmaf(__ldg(&hs[lane + 32]), nm, a1);
    }

    float m = (lane < 8) ? fmaxf(a0, a1) : a0;
#pragma unroll
    for (int o = 16; o >= 1; o >>= 1)
        m = fmaxf(m, __shfl_xor_sync(0xFFFFFFFFu, m, o));
    float s = __expf(a0 - m) + ((lane < 8) ? __expf(a1 - m) : 0.f);
#pragma unroll
    for (int o = 16; o >= 1; o >>= 1)
        s += __shfl_xor_sync(0xFFFFFFFFu, s, o);
    float ls = m + logf(s);

    float* op = out + (size_t)node * NC;
    op[lane] = a0 - ls;
    if (lane < 8) op[lane + 32] = a1 - ls;
}

// ---------------- launch ----------------
extern "C" void kernel_launch(void* const* d_in, const int* in_sizes, int n_in,
                              void* d_out, int out_size) {
    const float* x  = (const float*)d_in[0];
    const int*   ei = (const int*)d_in[1];
    const float* ew = (const float*)d_in[2];
    const float* W1 = (const float*)d_in[3];
    const float* b1 = (const float*)d_in[4];
    const float* W2 = (const float*)d_in[5];
    const float* b2 = (const float*)d_in[6];
    float* out = (float*)d_out;

    const int* src = ei;
    const int* dst = ei + N_EDGES;

    k_init<<<(N_NODES + 255) / 256, 256>>>();
    k_cnt<<<(N_EDGES + 255) / 256, 256>>>(dst, ew);
    k_fin<<<(N_NODES + 255) / 256, 256>>>();
    k_scan<<<1, 1024>>>();
    k_fill<<<(N_EDGES + 255) / 256, 256>>>(src, dst, ew);

    k_gemm1<<<dim3((N_NODES + 127) / 128, 2), 256>>>(x, W1, b1);
    k_agg1<<<(2 * N_NODES + 7) / 8, 256>>>();
    k_gemm2<<<(N_NODES + 63) / 64, 256>>>(W2, b2);
    k_agg2_lsm<<<(N_NODES + 7) / 8, 256>>>(out);
}

// round 6
// speedup vs baseline: 1.4221x; 1.1187x over previous
#include <cuda_runtime.h>
#include <math.h>

#define N_NODES 100000
#define N_EDGES 1600000
#define F_IN 256
#define HID 256
#define NC 40

// ---------------- scratch (static device globals; no allocation) ----------------
__device__ float g_dis[N_NODES];                  // deg -> deg^{-1/2}
__device__ int   g_cnt[N_NODES];                  // incoming-edge counts
__device__ int   g_off[N_NODES];                  // CSR segment starts (atomic-allocated)
__device__ int   g_cur[N_NODES];                  // fill cursors
__device__ int   g_total;                         // allocation counter
__device__ int   g_ssrc[N_EDGES];                 // src grouped by dst
__device__ float g_snorm[N_EDGES];                // norm grouped by dst
__device__ float g_h1[(size_t)N_NODES * HID];     // x @ W1 + b1
__device__ float g_a1[(size_t)N_NODES * HID];     // relu(aggregated layer 1)
__device__ float g_h2[(size_t)N_NODES * NC];      // a1 @ W2 + b2

// ---------------- init: deg=1 (self loop), counters=0 ----------------
__global__ void k_init() {
    int i = blockIdx.x * blockDim.x + threadIdx.x;
    if (i < N_NODES) { g_dis[i] = 1.0f; g_cnt[i] = 0; g_cur[i] = 0; }
    if (i == 0) g_total = 0;
}

__global__ void k_cnt(const int* __restrict__ dst, const float* __restrict__ ew) {
    int e = blockIdx.x * blockDim.x + threadIdx.x;
    if (e < N_EDGES) {
        int d = dst[e];
        atomicAdd(&g_dis[d], ew[e]);
        atomicAdd(&g_cnt[d], 1);
    }
}

// ---------------- finalize deg^{-1/2} AND allocate CSR segments ----------------
__global__ void k_fin() {
    int i = blockIdx.x * blockDim.x + threadIdx.x;
    if (i < N_NODES) {
        g_dis[i] = rsqrtf(g_dis[i]);              // deg >= 1 always
        g_off[i] = atomicAdd(&g_total, g_cnt[i]); // private contiguous range per node
    }
}

// ---------------- fill CSR with (src, norm) ----------------
__global__ void k_fill(const int* __restrict__ src, const int* __restrict__ dst,
                       const float* __restrict__ ew) {
    int e = blockIdx.x * blockDim.x + threadIdx.x;
    if (e >= N_EDGES) return;
    int d = dst[e];
    int s = src[e];
    int pos = g_off[d] + atomicAdd(&g_cur[d], 1);
    g_ssrc[pos] = s;
    g_snorm[pos] = g_dis[s] * ew[e] * g_dis[d];
}

// ---------------- GEMM1: g_h1 = x @ W1 + b1   (M=100000, K=256, N=256) ----------------
__global__ __launch_bounds__(256, 2) void k_gemm1(const float* __restrict__ A,
                                                  const float* __restrict__ B,
                                                  const float* __restrict__ bias) {
    __shared__ float As[16][128];
    __shared__ float Bs[16][128];

    const int tid = threadIdx.x;
    const int tx = tid % 16;
    const int ty = tid / 16;
    const int rowBase = blockIdx.x * 128;
    const int colBase = blockIdx.y * 128;

    float acc[8][8];
#pragma unroll
    for (int i = 0; i < 8; i++)
#pragma unroll
        for (int j = 0; j < 8; j++) acc[i][j] = 0.0f;

    for (int k0 = 0; k0 < 256; k0 += 16) {
#pragma unroll
        for (int l = 0; l < 2; l++) {
            int idx = tid + l * 256;
            int r = idx >> 2;
            int c4 = idx & 3;
            float4 v = make_float4(0.f, 0.f, 0.f, 0.f);
            int gr = rowBase + r;
            if (gr < N_NODES)
                v = *(const float4*)(A + (size_t)gr * 256 + k0 + c4 * 4);
            As[c4 * 4 + 0][r] = v.x;
            As[c4 * 4 + 1][r] = v.y;
            As[c4 * 4 + 2][r] = v.z;
            As[c4 * 4 + 3][r] = v.w;
        }
#pragma unroll
        for (int l = 0; l < 2; l++) {
            int idx = tid + l * 256;
            int r = idx >> 5;
            int c4 = idx & 31;
            float4 v = *(const float4*)(B + (size_t)(k0 + r) * 256 + colBase + c4 * 4);
            *(float4*)&Bs[r][c4 * 4] = v;
        }
        __syncthreads();

#pragma unroll
        for (int k = 0; k < 16; k++) {
            float ar[8], br[8];
#pragma unroll
            for (int i = 0; i < 8; i++) ar[i] = As[k][ty * 8 + i];
#pragma unroll
            for (int j = 0; j < 8; j++) br[j] = Bs[k][tx * 8 + j];
#pragma unroll
            for (int i = 0; i < 8; i++)
#pragma unroll
                for (int j = 0; j < 8; j++) acc[i][j] = fmaf(ar[i], br[j], acc[i][j]);
        }
        __syncthreads();
    }

#pragma unroll
    for (int i = 0; i < 8; i++) {
        int gr = rowBase + ty * 8 + i;
        if (gr < N_NODES) {
#pragma unroll
            for (int j = 0; j < 8; j++) {
                int gc = colBase + tx * 8 + j;
                g_h1[(size_t)gr * 256 + gc] = acc[i][j] + bias[gc];
            }
        }
    }
}

// ---------------- agg1: 2 warps per dst node (128 features each), CSR gather, relu ----------------
__global__ __launch_bounds__(256) void k_agg1() {
    int wid = blockIdx.x * 8 + (threadIdx.x >> 5);   // global warp id
    int node = wid >> 1;
    if (node >= N_NODES) return;
    int half = wid & 1;                               // 0: feats 0..127, 1: 128..255
    int lane = threadIdx.x & 31;
    int fo = half * 32 + lane;                        // float4 index within row (0..63)

    float dv = g_dis[node];
    float self = dv * dv;
    float4 acc = ((const float4*)(g_h1 + (size_t)node * HID))[fo];
    acc.x *= self; acc.y *= self; acc.z *= self; acc.w *= self;

    int beg = g_off[node], end = beg + g_cnt[node];
    for (int p = beg; p < end; p++) {
        int s = __ldg(&g_ssrc[p]);       // warp-uniform broadcast
        float nm = __ldg(&g_snorm[p]);
        float4 v = ((const float4*)(g_h1 + (size_t)s * HID))[fo];
        acc.x = fmaf(v.x, nm, acc.x);
        acc.y = fmaf(v.y, nm, acc.y);
        acc.z = fmaf(v.z, nm, acc.z);
        acc.w = fmaf(v.w, nm, acc.w);
    }

    acc.x = fmaxf(acc.x, 0.f); acc.y = fmaxf(acc.y, 0.f);
    acc.z = fmaxf(acc.z, 0.f); acc.w = fmaxf(acc.w, 0.f);
    ((float4*)(g_a1 + (size_t)node * HID))[fo] = acc;
}

// ---------------- GEMM2: g_h2 = a1 @ W2 + b2  (a1 already relu'd) ----------------
__global__ __launch_bounds__(256) void k_gemm2(const float* __restrict__ W2,
                                               const float* __restrict__ b2) {
    __shared__ float sW[HID * NC];  // 40 KB
    for (int i = threadIdx.x; i < HID * NC; i += 256) sW[i] = W2[i];
    __syncthreads();

    int row = blockIdx.x * 64 + (threadIdx.x >> 2);
    int cg = (threadIdx.x & 3) * 10;
    if (row >= N_NODES) return;

    float acc[10];
#pragma unroll
    for (int c = 0; c < 10; c++) acc[c] = b2[cg + c];

    const float4* a = (const float4*)(g_a1 + (size_t)row * HID);
    for (int k4 = 0; k4 < HID / 4; k4++) {
        float4 av = a[k4];
        float v[4] = {av.x, av.y, av.z, av.w};
#pragma unroll
        for (int kk = 0; kk < 4; kk++) {
            int k = k4 * 4 + kk;
#pragma unroll
            for (int c = 0; c < 10; c++)
                acc[c] = fmaf(v[kk], sW[k * NC + cg + c], acc[c]);
        }
    }
#pragma unroll
    for (int c = 0; c < 10; c++) g_h2[(size_t)row * NC + cg + c] = acc[c];
}

// ---------------- agg2 + log_softmax fused: warp per dst node ----------------
__global__ __launch_bounds__(256) void k_agg2_lsm(float* __restrict__ out) {
    int node = blockIdx.x * 8 + (threadIdx.x >> 5);
    if (node >= N_NODES) return;
    int lane = threadIdx.x & 31;

    float dv = g_dis[node];
    float self = dv * dv;
    const float* hd = g_h2 + (size_t)node * NC;
    float a0 = hd[lane] * self;                          // classes 0..31
    float a1 = (lane < 8) ? hd[lane + 32] * self : 0.f;  // classes 32..39

    int beg = g_off[node], end = beg + g_cnt[node];
    for (int p = beg; p < end; p++) {
        int s = __ldg(&g_ssrc[p]);
        float nm = __ldg(&g_snorm[p]);
        const float* hs = g_h2 + (size_t)s * NC;
        a0 = fmaf(__ldg(&hs[lane]), nm, a0);
        if (lane < 8) a1 = fmaf(__ldg(&hs[lane + 32]), nm, a1);
    }

    float m = (lane < 8) ? fmaxf(a0, a1) : a0;
#pragma unroll
    for (int o = 16; o >= 1; o >>= 1)
        m = fmaxf(m, __shfl_xor_sync(0xFFFFFFFFu, m, o));
    float s = __expf(a0 - m) + ((lane < 8) ? __expf(a1 - m) : 0.f);
#pragma unroll
    for (int o = 16; o >= 1; o >>= 1)
        s += __shfl_xor_sync(0xFFFFFFFFu, s, o);
    float ls = m + logf(s);

    float* op = out + (size_t)node * NC;
    op[lane] = a0 - ls;
    if (lane < 8) op[lane + 32] = a1 - ls;
}

// ---------------- launch ----------------
extern "C" void kernel_launch(void* const* d_in, const int* in_sizes, int n_in,
                              void* d_out, int out_size) {
    const float* x  = (const float*)d_in[0];
    const int*   ei = (const int*)d_in[1];
    const float* ew = (const float*)d_in[2];
    const float* W1 = (const float*)d_in[3];
    const float* b1 = (const float*)d_in[4];
    const float* W2 = (const float*)d_in[5];
    const float* b2 = (const float*)d_in[6];
    float* out = (float*)d_out;

    const int* src = ei;
    const int* dst = ei + N_EDGES;

    k_init<<<(N_NODES + 255) / 256, 256>>>();
    k_cnt<<<(N_EDGES + 255) / 256, 256>>>(dst, ew);
    k_fin<<<(N_NODES + 255) / 256, 256>>>();
    k_fill<<<(N_EDGES + 255) / 256, 256>>>(src, dst, ew);

    k_gemm1<<<dim3((N_NODES + 127) / 128, 2), 256>>>(x, W1, b1);
    k_agg1<<<(2 * N_NODES + 7) / 8, 256>>>();
    k_gemm2<<<(N_NODES + 63) / 64, 256>>>(W2, b2);
    k_agg2_lsm<<<(N_NODES + 7) / 8, 256>>>(out);
}

// round 8
// speedup vs baseline: 1.9054x; 1.3399x over previous
#include <cuda_runtime.h>
#include <cuda_bf16.h>
#include <math.h>
#include <cstdint>

#define N_NODES 100000
#define N_EDGES 1600000
#define F_IN 256
#define HID 256
#define NC 40

// ---------------- scratch (static device globals; no allocation) ----------------
__device__ float g_dis[N_NODES];
__device__ int   g_cnt[N_NODES];
__device__ int   g_off[N_NODES];
__device__ int   g_cur[N_NODES];
__device__ int   g_total;
__device__ int   g_ssrc[N_EDGES];
__device__ float g_snorm[N_EDGES];
__device__ float g_h1[(size_t)N_NODES * HID];
__device__ float g_a1[(size_t)N_NODES * HID];
__device__ float g_h2[(size_t)N_NODES * NC];
// W1 transposed + bf16-split: [N=256][K=256]
__device__ __nv_bfloat16 g_w1t_hi[256 * 256];
__device__ __nv_bfloat16 g_w1t_lo[256 * 256];

// ---------------- preprocessing ----------------
__global__ void k_init() {
    int i = blockIdx.x * blockDim.x + threadIdx.x;
    if (i < N_NODES) { g_dis[i] = 1.0f; g_cnt[i] = 0; g_cur[i] = 0; }
    if (i == 0) g_total = 0;
}

__global__ void k_cnt(const int* __restrict__ dst, const float* __restrict__ ew) {
    int e = blockIdx.x * blockDim.x + threadIdx.x;
    if (e < N_EDGES) {
        int d = dst[e];
        atomicAdd(&g_dis[d], ew[e]);
        atomicAdd(&g_cnt[d], 1);
    }
}

__global__ void k_fin() {
    int i = blockIdx.x * blockDim.x + threadIdx.x;
    if (i < N_NODES) {
        g_dis[i] = rsqrtf(g_dis[i]);
        g_off[i] = atomicAdd(&g_total, g_cnt[i]);
    }
}

__global__ void k_fill(const int* __restrict__ src, const int* __restrict__ dst,
                       const float* __restrict__ ew) {
    int e = blockIdx.x * blockDim.x + threadIdx.x;
    if (e >= N_EDGES) return;
    int d = dst[e];
    int s = src[e];
    int pos = g_off[d] + atomicAdd(&g_cur[d], 1);
    g_ssrc[pos] = s;
    g_snorm[pos] = g_dis[s] * ew[e] * g_dis[d];
}

// ---------------- W1 transpose + bf16 split: g_w1t[n*256+k] = W1[k*256+n] ----------------
__global__ void k_w1t(const float* __restrict__ W1) {
    int t = blockIdx.x * blockDim.x + threadIdx.x;
    if (t >= 256 * 256) return;
    int n = t >> 8, k = t & 255;
    float w = W1[k * 256 + n];
    __nv_bfloat16 hi = __float2bfloat16(w);
    __nv_bfloat16 lo = __float2bfloat16(w - __bfloat162float(hi));
    g_w1t_hi[t] = hi;
    g_w1t_lo[t] = lo;
}

// ---------------- mma.sync m16n8k16 bf16 helper ----------------
__device__ __forceinline__ void mma16816(float* c, const uint32_t* a, const uint32_t* b) {
    asm volatile(
        "mma.sync.aligned.m16n8k16.row.col.f32.bf16.bf16.f32 "
        "{%0,%1,%2,%3}, {%4,%5,%6,%7}, {%8,%9}, {%0,%1,%2,%3};\n"
        : "+f"(c[0]), "+f"(c[1]), "+f"(c[2]), "+f"(c[3])
        : "r"(a[0]), "r"(a[1]), "r"(a[2]), "r"(a[3]), "r"(b[0]), "r"(b[1]));
}

// ---------------- GEMM1 via mma.sync: g_h1 = x @ W1 + b1 ----------------
// CTA 128x128, 8 warps (2 m x 4 n), warp tile 64x32.
// bf16 2-term split: hi*hi + hi*lo + lo*hi, fp32 accumulate.
#define SA 72                    // smem row stride in bf16 (144 B = 9 banks, conflict-free)
#define SM_AH 0
#define SM_AL (SM_AH + 128 * SA * 2)
#define SM_BH (SM_AL + 128 * SA * 2)
#define SM_BL (SM_BH + 128 * SA * 2)
#define SM_G1 (SM_BL + 128 * SA * 2)    // 73728 bytes total

__global__ __launch_bounds__(256, 2) void k_gemm1_mma(const float* __restrict__ A,
                                                      const float* __restrict__ bias) {
    extern __shared__ char smem[];
    __nv_bfloat16* Ah = (__nv_bfloat16*)(smem + SM_AH);
    __nv_bfloat16* Al = (__nv_bfloat16*)(smem + SM_AL);
    __nv_bfloat16* Bh = (__nv_bfloat16*)(smem + SM_BH);
    __nv_bfloat16* Bl = (__nv_bfloat16*)(smem + SM_BL);

    const int tid = threadIdx.x;
    const int warp = tid >> 5;
    const int lane = tid & 31;
    const int g = lane >> 2;          // 0..7
    const int tg = lane & 3;          // 0..3
    const int wm = (warp >> 2) * 64;  // warp m offset in tile
    const int wn = (warp & 3) * 32;   // warp n offset in tile
    const int rowBase = blockIdx.x * 128;
    const int colBase = blockIdx.y * 128;

    float acc[4][4][4];
#pragma unroll
    for (int i = 0; i < 4; i++)
#pragma unroll
        for (int j = 0; j < 4; j++)
#pragma unroll
            for (int r = 0; r < 4; r++) acc[i][j][r] = 0.0f;

    for (int ch = 0; ch < 4; ch++) {
        const int k0 = ch * 64;
        // A chunk: 128 rows x 64 k fp32 -> hi/lo bf16 into smem (stride SA)
#pragma unroll
        for (int i = 0; i < 8; i++) {
            int idx = tid + i * 256;
            int r = idx >> 4, c4 = idx & 15;     // 16 float4 per row
            int gr = rowBase + r;
            float4 v = make_float4(0.f, 0.f, 0.f, 0.f);
            if (gr < N_NODES) v = *(const float4*)(A + (size_t)gr * 256 + k0 + c4 * 4);
            __nv_bfloat16 hx = __float2bfloat16(v.x), hy = __float2bfloat16(v.y);
            __nv_bfloat16 hz = __float2bfloat16(v.z), hw = __float2bfloat16(v.w);
            __nv_bfloat16 lx = __float2bfloat16(v.x - __bfloat162float(hx));
            __nv_bfloat16 ly = __float2bfloat16(v.y - __bfloat162float(hy));
            __nv_bfloat16 lz = __float2bfloat16(v.z - __bfloat162float(hz));
            __nv_bfloat16 lw = __float2bfloat16(v.w - __bfloat162float(hw));
            int o = r * SA + c4 * 4;
            *(__nv_bfloat162*)(Ah + o)     = __halves2bfloat162(hx, hy);
            *(__nv_bfloat162*)(Ah + o + 2) = __halves2bfloat162(hz, hw);
            *(__nv_bfloat162*)(Al + o)     = __halves2bfloat162(lx, ly);
            *(__nv_bfloat162*)(Al + o + 2) = __halves2bfloat162(lz, lw);
        }
        // B chunk: 128 n-rows x 64 k bf16 (pre-split) into smem (stride SA)
#pragma unroll
        for (int i = 0; i < 4; i++) {
            int idx = tid + i * 256;
            int r = idx >> 3, u = idx & 7;       // 8 uint4 per row
            int o = r * SA + u * 8;
            *(uint4*)(Bh + o) = *(const uint4*)(g_w1t_hi + (size_t)(colBase + r) * 256 + k0 + u * 8);
            *(uint4*)(Bl + o) = *(const uint4*)(g_w1t_lo + (size_t)(colBase + r) * 256 + k0 + u * 8);
        }
        __syncthreads();

#pragma unroll
        for (int ks = 0; ks < 4; ks++) {
            const int kb = ks * 16;
            uint32_t bh[4][2], bl[4][2];
#pragma unroll
            for (int j = 0; j < 4; j++) {
                int n = wn + j * 8 + g;
                bh[j][0] = *(const uint32_t*)(Bh + n * SA + kb + tg * 2);
                bh[j][1] = *(const uint32_t*)(Bh + n * SA + kb + tg * 2 + 8);
                bl[j][0] = *(const uint32_t*)(Bl + n * SA + kb + tg * 2);
                bl[j][1] = *(const uint32_t*)(Bl + n * SA + kb + tg * 2 + 8);
            }
#pragma unroll
            for (int i = 0; i < 4; i++) {
                int m = wm + i * 16;
                uint32_t ah[4], al[4];
                ah[0] = *(const uint32_t*)(Ah + (m + g) * SA + kb + tg * 2);
                ah[1] = *(const uint32_t*)(Ah + (m + g + 8) * SA + kb + tg * 2);
                ah[2] = *(const uint32_t*)(Ah + (m + g) * SA + kb + tg * 2 + 8);
                ah[3] = *(const uint32_t*)(Ah + (m + g + 8) * SA + kb + tg * 2 + 8);
                al[0] = *(const uint32_t*)(Al + (m + g) * SA + kb + tg * 2);
                al[1] = *(const uint32_t*)(Al + (m + g + 8) * SA + kb + tg * 2);
                al[2] = *(const uint32_t*)(Al + (m + g) * SA + kb + tg * 2 + 8);
                al[3] = *(const uint32_t*)(Al + (m + g + 8) * SA + kb + tg * 2 + 8);
#pragma unroll
                for (int j = 0; j < 4; j++) {
                    mma16816(acc[i][j], ah, bh[j]);
                    mma16816(acc[i][j], ah, bl[j]);
                    mma16816(acc[i][j], al, bh[j]);
                }
            }
        }
        __syncthreads();
    }

    // epilogue: c0->D[g][tg*2], c1->D[g][tg*2+1], c2->D[g+8][tg*2], c3->D[g+8][tg*2+1]
#pragma unroll
    for (int j = 0; j < 4; j++) {
        int col = colBase + wn + j * 8 + tg * 2;
        float bx = __ldg(&bias[col]);
        float by = __ldg(&bias[col + 1]);
#pragma unroll
        for (int i = 0; i < 4; i++) {
            int r0 = rowBase + wm + i * 16 + g;
            if (r0 < N_NODES) {
                float2 v = make_float2(acc[i][j][0] + bx, acc[i][j][1] + by);
                *(float2*)(g_h1 + (size_t)r0 * 256 + col) = v;
            }
            int r1 = r0 + 8;
            if (r1 < N_NODES) {
                float2 v = make_float2(acc[i][j][2] + bx, acc[i][j][3] + by);
                *(float2*)(g_h1 + (size_t)r1 * 256 + col) = v;
            }
        }
    }
}

// ---------------- agg1: 2 warps per dst node, CSR gather, relu ----------------
__global__ __launch_bounds__(256) void k_agg1() {
    int wid = blockIdx.x * 8 + (threadIdx.x >> 5);
    int node = wid >> 1;
    if (node >= N_NODES) return;
    int half = wid & 1;
    int lane = threadIdx.x & 31;
    int fo = half * 32 + lane;

    float dv = g_dis[node];
    float self = dv * dv;
    float4 acc = ((const float4*)(g_h1 + (size_t)node * HID))[fo];
    acc.x *= self; acc.y *= self; acc.z *= self; acc.w *= self;

    int beg = g_off[node], end = beg + g_cnt[node];
    for (int p = beg; p < end; p++) {
        int s = __ldg(&g_ssrc[p]);
        float nm = __ldg(&g_snorm[p]);
        float4 v = ((const float4*)(g_h1 + (size_t)s * HID))[fo];
        acc.x = fmaf(v.x, nm, acc.x);
        acc.y = fmaf(v.y, nm, acc.y);
        acc.z = fmaf(v.z, nm, acc.z);
        acc.w = fmaf(v.w, nm, acc.w);
    }

    acc.x = fmaxf(acc.x, 0.f); acc.y = fmaxf(acc.y, 0.f);
    acc.z = fmaxf(acc.z, 0.f); acc.w = fmaxf(acc.w, 0.f);
    ((float4*)(g_a1 + (size_t)node * HID))[fo] = acc;
}

// ---------------- GEMM2: g_h2 = a1 @ W2 + b2 ----------------
__global__ __launch_bounds__(256) void k_gemm2(const float* __restrict__ W2,
                                               const float* __restrict__ b2) {
    __shared__ float sW[HID * NC];
    for (int i = threadIdx.x; i < HID * NC; i += 256) sW[i] = W2[i];
    __syncthreads();

    int row = blockIdx.x * 64 + (threadIdx.x >> 2);
    int cg = (threadIdx.x & 3) * 10;
    if (row >= N_NODES) return;

    float acc[10];
#pragma unroll
    for (int c = 0; c < 10; c++) acc[c] = b2[cg + c];

    const float4* a = (const float4*)(g_a1 + (size_t)row * HID);
    for (int k4 = 0; k4 < HID / 4; k4++) {
        float4 av = a[k4];
        float v[4] = {av.x, av.y, av.z, av.w};
#pragma unroll
        for (int kk = 0; kk < 4; kk++) {
            int k = k4 * 4 + kk;
#pragma unroll
            for (int c = 0; c < 10; c++)
                acc[c] = fmaf(v[kk], sW[k * NC + cg + c], acc[c]);
        }
    }
#pragma unroll
    for (int c = 0; c < 10; c++) g_h2[(size_t)row * NC + cg + c] = acc[c];
}

// ---------------- agg2 + log_softmax fused ----------------
__global__ __launch_bounds__(256) void k_agg2_lsm(float* __restrict__ out) {
    int node = blockIdx.x * 8 + (threadIdx.x >> 5);
    if (node >= N_NODES) return;
    int lane = threadIdx.x & 31;

    float dv = g_dis[node];
    float self = dv * dv;
    const float* hd = g_h2 + (size_t)node * NC;
    float a0 = hd[lane] * self;
    float a1 = (lane < 8) ? hd[lane + 32] * self : 0.f;

    int beg = g_off[node], end = beg + g_cnt[node];
    for (int p = beg; p < end; p++) {
        int s = __ldg(&g_ssrc[p]);
        float nm = __ldg(&g_snorm[p]);
        const float* hs = g_h2 + (size_t)s * NC;
        a0 = fmaf(__ldg(&hs[lane]), nm, a0);
        if (lane < 8) a1 = fmaf(__ldg(&hs[lane + 32]), nm, a1);
    }

    float m = (lane < 8) ? fmaxf(a0, a1) : a0;
#pragma unroll
    for (int o = 16; o >= 1; o >>= 1)
        m = fmaxf(m, __shfl_xor_sync(0xFFFFFFFFu, m, o));
    float s = __expf(a0 - m) + ((lane < 8) ? __expf(a1 - m) : 0.f);
#pragma unroll
    for (int o = 16; o >= 1; o >>= 1)
        s += __shfl_xor_sync(0xFFFFFFFFu, s, o);
    float ls = m + logf(s);

    float* op = out + (size_t)node * NC;
    op[lane] = a0 - ls;
    if (lane < 8) op[lane + 32] = a1 - ls;
}

// ---------------- launch ----------------
extern "C" void kernel_launch(void* const* d_in, const int* in_sizes, int n_in,
                              void* d_out, int out_size) {
    const float* x  = (const float*)d_in[0];
    const int*   ei = (const int*)d_in[1];
    const float* ew = (const float*)d_in[2];
    const float* W1 = (const float*)d_in[3];
    const float* b1 = (const float*)d_in[4];
    const float* W2 = (const float*)d_in[5];
    const float* b2 = (const float*)d_in[6];
    float* out = (float*)d_out;

    const int* src = ei;
    const int* dst = ei + N_EDGES;

    cudaFuncSetAttribute(k_gemm1_mma, cudaFuncAttributeMaxDynamicSharedMemorySize, SM_G1);

    k_init<<<(N_NODES + 255) / 256, 256>>>();
    k_cnt<<<(N_EDGES + 255) / 256, 256>>>(dst, ew);
    k_fin<<<(N_NODES + 255) / 256, 256>>>();
    k_fill<<<(N_EDGES + 255) / 256, 256>>>(src, dst, ew);
    k_w1t<<<256, 256>>>(W1);

    k_gemm1_mma<<<dim3((N_NODES + 127) / 128, 2), 256, SM_G1>>>(x, b1);
    k_agg1<<<(2 * N_NODES + 7) / 8, 256>>>();
    k_gemm2<<<(N_NODES + 63) / 64, 256>>>(W2, b2);
    k_agg2_lsm<<<(N_NODES + 7) / 8, 256>>>(out);
}

// round 10
// speedup vs baseline: 1.9191x; 1.0072x over previous
#include <cuda_runtime.h>
#include <cuda_bf16.h>
#include <math.h>
#include <cstdint>

#define N_NODES 100000
#define N_EDGES 1600000
#define N_PAD 100096            // 782 * 128
#define F_IN 256
#define HID 256
#define NC 40

// ---------------- scratch (static device globals; no allocation) ----------------
__device__ float g_dis[N_NODES];
__device__ int   g_cnt[N_NODES];
__device__ int   g_off[N_NODES];
__device__ int   g_cur[N_NODES];
__device__ int   g_total;
__device__ int   g_ssrc[N_EDGES];
__device__ float g_snorm[N_EDGES];
__device__ float g_h1[(size_t)N_NODES * HID];
__device__ float g_a1[(size_t)N_NODES * HID];
__device__ float g_h2[(size_t)N_NODES * NC];
// bf16 splits
__device__ __nv_bfloat16 g_w1t_hi[256 * 256];   // W1^T [n][k]
__device__ __nv_bfloat16 g_w1t_lo[256 * 256];
__device__ __nv_bfloat16 g_xh[(size_t)N_PAD * 256];
__device__ __nv_bfloat16 g_xl[(size_t)N_PAD * 256];

__device__ __forceinline__ uint32_t smem_u32(const void* p) {
    uint32_t a;
    asm("{ .reg .u64 t; cvta.to.shared.u64 t, %1; cvt.u32.u64 %0, t; }" : "=r"(a) : "l"(p));
    return a;
}
#define CPA16(dst, src) asm volatile("cp.async.cg.shared.global [%0], [%1], 16;" :: "r"(dst), "l"(src))
#define CPC()  asm volatile("cp.async.commit_group;" ::: "memory")
#define CPW(n) asm volatile("cp.async.wait_group %0;" :: "n"(n) : "memory")

// ---------------- preprocessing ----------------
__global__ void k_init() {
    int i = blockIdx.x * blockDim.x + threadIdx.x;
    if (i < N_NODES) { g_dis[i] = 1.0f; g_cnt[i] = 0; g_cur[i] = 0; }
    if (i == 0) g_total = 0;
}

__global__ void k_cnt(const int* __restrict__ dst, const float* __restrict__ ew) {
    int e = blockIdx.x * blockDim.x + threadIdx.x;
    if (e < N_EDGES) {
        int d = dst[e];
        atomicAdd(&g_dis[d], ew[e]);
        atomicAdd(&g_cnt[d], 1);
    }
}

__global__ void k_fin() {
    int i = blockIdx.x * blockDim.x + threadIdx.x;
    if (i < N_NODES) {
        g_dis[i] = rsqrtf(g_dis[i]);
        g_off[i] = atomicAdd(&g_total, g_cnt[i]);
    }
}

__global__ void k_fill(const int* __restrict__ src, const int* __restrict__ dst,
                       const float* __restrict__ ew) {
    int e = blockIdx.x * blockDim.x + threadIdx.x;
    if (e >= N_EDGES) return;
    int d = dst[e];
    int s = src[e];
    int pos = g_off[d] + atomicAdd(&g_cur[d], 1);
    g_ssrc[pos] = s;
    g_snorm[pos] = g_dis[s] * ew[e] * g_dis[d];
}

// ---------------- W1 transpose + bf16 split ----------------
__global__ void k_w1t(const float* __restrict__ W1) {
    int t = blockIdx.x * blockDim.x + threadIdx.x;
    if (t >= 256 * 256) return;
    int n = t >> 8, k = t & 255;
    float w = W1[k * 256 + n];
    __nv_bfloat16 hi = __float2bfloat16(w);
    __nv_bfloat16 lo = __float2bfloat16(w - __bfloat162float(hi));
    g_w1t_hi[t] = hi;
    g_w1t_lo[t] = lo;
}

// ---------------- x bf16 split (padded) ----------------
__global__ void k_xsplit(const float* __restrict__ x) {
    int t = blockIdx.x * blockDim.x + threadIdx.x;   // one float4 (4 features)
    if (t >= N_PAD * 64) return;
    int node = t >> 6;
    float4 v = make_float4(0.f, 0.f, 0.f, 0.f);
    if (node < N_NODES) v = ((const float4*)x)[t];
    __nv_bfloat16 hx = __float2bfloat16(v.x), hy = __float2bfloat16(v.y);
    __nv_bfloat16 hz = __float2bfloat16(v.z), hw = __float2bfloat16(v.w);
    __nv_bfloat16 lx = __float2bfloat16(v.x - __bfloat162float(hx));
    __nv_bfloat16 ly = __float2bfloat16(v.y - __bfloat162float(hy));
    __nv_bfloat16 lz = __float2bfloat16(v.z - __bfloat162float(hz));
    __nv_bfloat16 lw = __float2bfloat16(v.w - __bfloat162float(hw));
    ((__nv_bfloat162*)g_xh)[t * 2]     = __halves2bfloat162(hx, hy);
    ((__nv_bfloat162*)g_xh)[t * 2 + 1] = __halves2bfloat162(hz, hw);
    ((__nv_bfloat162*)g_xl)[t * 2]     = __halves2bfloat162(lx, ly);
    ((__nv_bfloat162*)g_xl)[t * 2 + 1] = __halves2bfloat162(lz, lw);
}

// ---------------- mma.sync m16n8k16 bf16 ----------------
__device__ __forceinline__ void mma16816(float* c, const uint32_t* a, const uint32_t* b) {
    asm volatile(
        "mma.sync.aligned.m16n8k16.row.col.f32.bf16.bf16.f32 "
        "{%0,%1,%2,%3}, {%4,%5,%6,%7}, {%8,%9}, {%0,%1,%2,%3};\n"
        : "+f"(c[0]), "+f"(c[1]), "+f"(c[2]), "+f"(c[3])
        : "r"(a[0]), "r"(a[1]), "r"(a[2]), "r"(a[3]), "r"(b[0]), "r"(b[1]));
}

// ---------------- GEMM1: 128x256 CTA, 512 threads, 2-stage cp.async pipeline ----------------
#define SA 72                              // bf16 row stride (144 B: 16B-aligned + conflict-free)
#define ST_AH 0
#define ST_AL (128 * SA * 2)               // 18432
#define ST_BH (2 * 128 * SA * 2)           // 36864
#define ST_BL (ST_BH + 256 * SA * 2)       // 73728
#define STAGE (ST_BL + 256 * SA * 2)       // 110592 bytes/stage
#define SM_G1 (2 * STAGE)                  // 221184 bytes

__global__ __launch_bounds__(512) void k_gemm1_mma(const float* __restrict__ bias) {
    extern __shared__ char smem[];
    const uint32_t sbase = smem_u32(smem);
    const int tid = threadIdx.x;
    const int warp = tid >> 5;
    const int lane = tid & 31;
    const int g = lane >> 2;
    const int tg = lane & 3;
    const int wm = (warp >> 3) * 64;       // 2 m-groups
    const int wn = (warp & 7) * 32;        // 8 n-groups
    const int rowBase = blockIdx.x * 128;

    // stage loader: A (128 rows x 64 k, hi+lo) + B (256 rows x 64 k, hi+lo)
    auto load_stage = [&](int ch, int buf) {
        const int k0 = ch * 64;
        const uint32_t base = sbase + buf * STAGE;
#pragma unroll
        for (int i = 0; i < 2; i++) {       // A: 1024 x 16B
            int idx = tid + i * 512;
            int r = idx >> 3, u = idx & 7;
            uint32_t d = base + ST_AH + (uint32_t)(r * SA + u * 8) * 2;
            CPA16(d, g_xh + (size_t)(rowBase + r) * 256 + k0 + u * 8);
            CPA16(d + (ST_AL - ST_AH), g_xl + (size_t)(rowBase + r) * 256 + k0 + u * 8);
        }
#pragma unroll
        for (int i = 0; i < 4; i++) {       // B: 2048 x 16B
            int idx = tid + i * 512;
            int r = idx >> 3, u = idx & 7;
            uint32_t d = base + ST_BH + (uint32_t)(r * SA + u * 8) * 2;
            CPA16(d, g_w1t_hi + r * 256 + k0 + u * 8);
            CPA16(d + (ST_BL - ST_BH), g_w1t_lo + r * 256 + k0 + u * 8);
        }
    };

    float acc[4][4][4];
#pragma unroll
    for (int i = 0; i < 4; i++)
#pragma unroll
        for (int j = 0; j < 4; j++)
#pragma unroll
            for (int r = 0; r < 4; r++) acc[i][j][r] = 0.0f;

    load_stage(0, 0);
    CPC();

    for (int ch = 0; ch < 4; ch++) {
        const int buf = ch & 1;
        if (ch < 3) { load_stage(ch + 1, buf ^ 1); CPC(); CPW(1); }
        else CPW(0);
        __syncthreads();

        const char* Ah = smem + buf * STAGE + ST_AH;
        const char* Al = smem + buf * STAGE + ST_AL;
        const char* Bh = smem + buf * STAGE + ST_BH;
        const char* Bl = smem + buf * STAGE + ST_BL;

#pragma unroll
        for (int ks = 0; ks < 4; ks++) {
            const int kb = ks * 16;
            uint32_t bh[4][2], bl[4][2];
#pragma unroll
            for (int j = 0; j < 4; j++) {
                int n = wn + j * 8 + g;
                int o = (n * SA + kb + tg * 2) * 2;
                bh[j][0] = *(const uint32_t*)(Bh + o);
                bh[j][1] = *(const uint32_t*)(Bh + o + 16);
                bl[j][0] = *(const uint32_t*)(Bl + o);
                bl[j][1] = *(const uint32_t*)(Bl + o + 16);
            }
#pragma unroll
            for (int i = 0; i < 4; i++) {
                int m = wm + i * 16;
                int o0 = ((m + g) * SA + kb + tg * 2) * 2;
                int o1 = ((m + g + 8) * SA + kb + tg * 2) * 2;
                uint32_t ah[4], al[4];
                ah[0] = *(const uint32_t*)(Ah + o0);
                ah[1] = *(const uint32_t*)(Ah + o1);
                ah[2] = *(const uint32_t*)(Ah + o0 + 16);
                ah[3] = *(const uint32_t*)(Ah + o1 + 16);
                al[0] = *(const uint32_t*)(Al + o0);
                al[1] = *(const uint32_t*)(Al + o1);
                al[2] = *(const uint32_t*)(Al + o0 + 16);
                al[3] = *(const uint32_t*)(Al + o1 + 16);
#pragma unroll
                for (int j = 0; j < 4; j++) {
                    mma16816(acc[i][j], ah, bh[j]);
                    mma16816(acc[i][j], ah, bl[j]);
                    mma16816(acc[i][j], al, bh[j]);
                }
            }
        }
        __syncthreads();
    }

    // epilogue
#pragma unroll
    for (int j = 0; j < 4; j++) {
        int col = wn + j * 8 + tg * 2;
        float bx = __ldg(&bias[col]);
        float by = __ldg(&bias[col + 1]);
#pragma unroll
        for (int i = 0; i < 4; i++) {
            int r0 = rowBase + wm + i * 16 + g;
            if (r0 < N_NODES) {
                float2 v = make_float2(acc[i][j][0] + bx, acc[i][j][1] + by);
                *(float2*)(g_h1 + (size_t)r0 * 256 + col) = v;
            }
            int r1 = r0 + 8;
            if (r1 < N_NODES) {
                float2 v = make_float2(acc[i][j][2] + bx, acc[i][j][3] + by);
                *(float2*)(g_h1 + (size_t)r1 * 256 + col) = v;
            }
        }
    }
}

// ---------------- agg1: 2 warps per dst node, CSR gather, relu, 2x unrolled ----------------
__global__ __launch_bounds__(256) void k_agg1() {
    int wid = blockIdx.x * 8 + (threadIdx.x >> 5);
    int node = wid >> 1;
    if (node >= N_NODES) return;
    int half = wid & 1;
    int lane = threadIdx.x & 31;
    int fo = half * 32 + lane;

    float dv = g_dis[node];
    float self = dv * dv;
    float4 acc = ((const float4*)(g_h1 + (size_t)node * HID))[fo];
    acc.x *= self; acc.y *= self; acc.z *= self; acc.w *= self;

    int p = g_off[node], end = p + g_cnt[node];
    for (; p + 2 <= end; p += 2) {
        int s0 = __ldg(&g_ssrc[p]);
        int s1 = __ldg(&g_ssrc[p + 1]);
        float n0 = __ldg(&g_snorm[p]);
        float n1 = __ldg(&g_snorm[p + 1]);
        float4 v0 = ((const float4*)(g_h1 + (size_t)s0 * HID))[fo];
        float4 v1 = ((const float4*)(g_h1 + (size_t)s1 * HID))[fo];
        acc.x = fmaf(v0.x, n0, acc.x); acc.y = fmaf(v0.y, n0, acc.y);
        acc.z = fmaf(v0.z, n0, acc.z); acc.w = fmaf(v0.w, n0, acc.w);
        acc.x = fmaf(v1.x, n1, acc.x); acc.y = fmaf(v1.y, n1, acc.y);
        acc.z = fmaf(v1.z, n1, acc.z); acc.w = fmaf(v1.w, n1, acc.w);
    }
    if (p < end) {
        int s = __ldg(&g_ssrc[p]);
        float nm = __ldg(&g_snorm[p]);
        float4 v = ((const float4*)(g_h1 + (size_t)s * HID))[fo];
        acc.x = fmaf(v.x, nm, acc.x); acc.y = fmaf(v.y, nm, acc.y);
        acc.z = fmaf(v.z, nm, acc.z); acc.w = fmaf(v.w, nm, acc.w);
    }

    acc.x = fmaxf(acc.x, 0.f); acc.y = fmaxf(acc.y, 0.f);
    acc.z = fmaxf(acc.z, 0.f); acc.w = fmaxf(acc.w, 0.f);
    ((float4*)(g_a1 + (size_t)node * HID))[fo] = acc;
}

// ---------------- GEMM2: g_h2 = a1 @ W2 + b2 ----------------
__global__ __launch_bounds__(256) void k_gemm2(const float* __restrict__ W2,
                                               const float* __restrict__ b2) {
    __shared__ float sW[HID * NC];
    for (int i = threadIdx.x; i < HID * NC; i += 256) sW[i] = W2[i];
    __syncthreads();

    int row = blockIdx.x * 64 + (threadIdx.x >> 2);
    int cg = (threadIdx.x & 3) * 10;
    if (row >= N_NODES) return;

    float acc[10];
#pragma unroll
    for (int c = 0; c < 10; c++) acc[c] = b2[cg + c];

    const float4* a = (const float4*)(g_a1 + (size_t)row * HID);
    for (int k4 = 0; k4 < HID / 4; k4++) {
        float4 av = a[k4];
        float v[4] = {av.x, av.y, av.z, av.w};
#pragma unroll
        for (int kk = 0; kk < 4; kk++) {
            int k = k4 * 4 + kk;
#pragma unroll
            for (int c = 0; c < 10; c++)
                acc[c] = fmaf(v[kk], sW[k * NC + cg + c], acc[c]);
        }
    }
#pragma unroll
    for (int c = 0; c < 10; c++) g_h2[(size_t)row * NC + cg + c] = acc[c];
}

// ---------------- agg2 + log_softmax fused ----------------
__global__ __launch_bounds__(256) void k_agg2_lsm(float* __restrict__ out) {
    int node = blockIdx.x * 8 + (threadIdx.x >> 5);
    if (node >= N_NODES) return;
    int lane = threadIdx.x & 31;

    float dv = g_dis[node];
    float self = dv * dv;
    const float* hd = g_h2 + (size_t)node * NC;
    float a0 = hd[lane] * self;
    float a1 = (lane < 8) ? hd[lane + 32] * self : 0.f;

    int beg = g_off[node], end = beg + g_cnt[node];
    for (int p = beg; p < end; p++) {
        int s = __ldg(&g_ssrc[p]);
        float nm = __ldg(&g_snorm[p]);
        const float* hs = g_h2 + (size_t)s * NC;
        a0 = fmaf(__ldg(&hs[lane]), nm, a0);
        if (lane < 8) a1 = fmaf(__ldg(&hs[lane + 32]), nm, a1);
    }

    float m = (lane < 8) ? fmaxf(a0, a1) : a0;
#pragma unroll
    for (int o = 16; o >= 1; o >>= 1)
        m = fmaxf(m, __shfl_xor_sync(0xFFFFFFFFu, m, o));
    float s = __expf(a0 - m) + ((lane < 8) ? __expf(a1 - m) : 0.f);
#pragma unroll
    for (int o = 16; o >= 1; o >>= 1)
        s += __shfl_xor_sync(0xFFFFFFFFu, s, o);
    float ls = m + logf(s);

    float* op = out + (size_t)node * NC;
    op[lane] = a0 - ls;
    if (lane < 8) op[lane + 32] = a1 - ls;
}

// ---------------- launch ----------------
extern "C" void kernel_launch(void* const* d_in, const int* in_sizes, int n_in,
                              void* d_out, int out_size) {
    const float* x  = (const float*)d_in[0];
    const int*   ei = (const int*)d_in[1];
    const float* ew = (const float*)d_in[2];
    const float* W1 = (const float*)d_in[3];
    const float* b1 = (const float*)d_in[4];
    const float* W2 = (const float*)d_in[5];
    const float* b2 = (const float*)d_in[6];
    float* out = (float*)d_out;

    const int* src = ei;
    const int* dst = ei + N_EDGES;

    cudaFuncSetAttribute(k_gemm1_mma, cudaFuncAttributeMaxDynamicSharedMemorySize, SM_G1);

    k_init<<<(N_NODES + 255) / 256, 256>>>();
    k_cnt<<<(N_EDGES + 255) / 256, 256>>>(dst, ew);
    k_fin<<<(N_NODES + 255) / 256, 256>>>();
    k_fill<<<(N_EDGES + 255) / 256, 256>>>(src, dst, ew);
    k_w1t<<<256, 256>>>(W1);
    k_xsplit<<<(N_PAD * 64 + 255) / 256, 256>>>(x);

    k_gemm1_mma<<<N_PAD / 128, 512, SM_G1>>>(b1);
    k_agg1<<<(2 * N_NODES + 7) / 8, 256>>>();
    k_gemm2<<<(N_NODES + 63) / 64, 256>>>(W2, b2);
    k_agg2_lsm<<<(N_NODES + 7) / 8, 256>>>(out);
}

// round 11
// speedup vs baseline: 2.0916x; 1.0899x over previous
#include <cuda_runtime.h>
#include <cuda_bf16.h>
#include <math.h>
#include <cstdint>

#define N_NODES 100000
#define N_EDGES 1600000
#define N_PAD 100096            // 782 * 128
#define F_IN 256
#define HID 256
#define NC 40

// ---------------- scratch (static device globals; no allocation) ----------------
__device__ float g_dis[N_NODES];
__device__ int   g_cnt[N_NODES];
__device__ int   g_off[N_NODES];
__device__ int   g_cur[N_NODES];
__device__ int   g_total;
__device__ int   g_ssrc[N_EDGES];
__device__ float g_snorm[N_EDGES];
__device__ float g_h1[(size_t)N_NODES * HID];
__device__ float g_a1[(size_t)N_NODES * HID];
__device__ float g_h2[(size_t)N_NODES * NC];
__device__ __nv_bfloat16 g_w1t_hi[256 * 256];   // W1^T [n][k]
__device__ __nv_bfloat16 g_w1t_lo[256 * 256];

__device__ __forceinline__ uint32_t smem_u32(const void* p) {
    uint32_t a;
    asm("{ .reg .u64 t; cvta.to.shared.u64 t, %1; cvt.u32.u64 %0, t; }" : "=r"(a) : "l"(p));
    return a;
}
#define CPA16(dst, src) asm volatile("cp.async.cg.shared.global [%0], [%1], 16;" :: "r"(dst), "l"(src))
#define CPC()  asm volatile("cp.async.commit_group;" ::: "memory")
#define CPW(n) asm volatile("cp.async.wait_group %0;" :: "n"(n) : "memory")

// ---------------- preprocessing ----------------
__global__ void k_init() {
    int i = blockIdx.x * blockDim.x + threadIdx.x;
    if (i < N_NODES) { g_dis[i] = 1.0f; g_cnt[i] = 0; g_cur[i] = 0; }
    if (i == 0) g_total = 0;
}

__global__ void k_cnt(const int* __restrict__ dst, const float* __restrict__ ew) {
    int e = blockIdx.x * blockDim.x + threadIdx.x;
    if (e < N_EDGES) {
        int d = dst[e];
        atomicAdd(&g_dis[d], ew[e]);
        atomicAdd(&g_cnt[d], 1);
    }
}

__global__ void k_fin() {
    int i = blockIdx.x * blockDim.x + threadIdx.x;
    if (i < N_NODES) {
        g_dis[i] = rsqrtf(g_dis[i]);
        g_off[i] = atomicAdd(&g_total, g_cnt[i]);
    }
}

__global__ void k_fill(const int* __restrict__ src, const int* __restrict__ dst,
                       const float* __restrict__ ew) {
    int e = blockIdx.x * blockDim.x + threadIdx.x;
    if (e >= N_EDGES) return;
    int d = dst[e];
    int s = src[e];
    int pos = g_off[d] + atomicAdd(&g_cur[d], 1);
    g_ssrc[pos] = s;
    g_snorm[pos] = g_dis[s] * ew[e] * g_dis[d];
}

// ---------------- W1 transpose + bf16 split ----------------
__global__ void k_w1t(const float* __restrict__ W1) {
    int t = blockIdx.x * blockDim.x + threadIdx.x;
    if (t >= 256 * 256) return;
    int n = t >> 8, k = t & 255;
    float w = W1[k * 256 + n];
    __nv_bfloat16 hi = __float2bfloat16(w);
    __nv_bfloat16 lo = __float2bfloat16(w - __bfloat162float(hi));
    g_w1t_hi[t] = hi;
    g_w1t_lo[t] = lo;
}

// ---------------- mma.sync m16n8k16 bf16 ----------------
__device__ __forceinline__ void mma16816(float* c, const uint32_t* a, const uint32_t* b) {
    asm volatile(
        "mma.sync.aligned.m16n8k16.row.col.f32.bf16.bf16.f32 "
        "{%0,%1,%2,%3}, {%4,%5,%6,%7}, {%8,%9}, {%0,%1,%2,%3};\n"
        : "+f"(c[0]), "+f"(c[1]), "+f"(c[2]), "+f"(c[3])
        : "r"(a[0]), "r"(a[1]), "r"(a[2]), "r"(a[3]), "r"(b[0]), "r"(b[1]));
}

// ---------------- GEMM1: 128x256 CTA, 512 threads ----------------
// A: fp32 x loaded to regs, inline hi/lo bf16 split, single-buffer smem.
// B: pre-split bf16 via 2-stage cp.async pipeline.
#define SA 72                               // bf16 row stride (conflict-light)
#define SM_AH 0
#define SM_AL (128 * SA * 2)                // 18432
#define SM_B0 (2 * 128 * SA * 2)            // 36864
#define BHALF (256 * SA * 2)                // 36864 (hi block within a stage)
#define BSTAGE (2 * BHALF)                  // 73728 per stage
#define SM_G1 (SM_B0 + 2 * BSTAGE)          // 184320 bytes

__global__ __launch_bounds__(512) void k_gemm1_mma(const float* __restrict__ x,
                                                   const float* __restrict__ bias) {
    extern __shared__ char smem[];
    const uint32_t sbase = smem_u32(smem);
    const int tid = threadIdx.x;
    const int warp = tid >> 5;
    const int lane = tid & 31;
    const int g = lane >> 2;
    const int tg = lane & 3;
    const int wm = (warp >> 3) * 64;        // 2 m-groups
    const int wn = (warp & 7) * 32;         // 8 n-groups
    const int rowBase = blockIdx.x * 128;

    float4 vr[4];                           // A staging regs (16 floats)
    auto ldgA = [&](int ch) {
        const int k0 = ch * 64;
#pragma unroll
        for (int i = 0; i < 4; i++) {
            int idx = tid + i * 512;
            int r = idx >> 4, c4 = idx & 15;
            int gr = rowBase + r;
            vr[i] = (gr < N_NODES) ? *(const float4*)(x + (size_t)gr * 256 + k0 + c4 * 4)
                                   : make_float4(0.f, 0.f, 0.f, 0.f);
        }
    };
    auto stsA = [&]() {
#pragma unroll
        for (int i = 0; i < 4; i++) {
            int idx = tid + i * 512;
            int r = idx >> 4, c4 = idx & 15;
            float4 v = vr[i];
            __nv_bfloat16 hx = __float2bfloat16(v.x), hy = __float2bfloat16(v.y);
            __nv_bfloat16 hz = __float2bfloat16(v.z), hw = __float2bfloat16(v.w);
            __nv_bfloat16 lx = __float2bfloat16(v.x - __bfloat162float(hx));
            __nv_bfloat16 ly = __float2bfloat16(v.y - __bfloat162float(hy));
            __nv_bfloat16 lz = __float2bfloat16(v.z - __bfloat162float(hz));
            __nv_bfloat16 lw = __float2bfloat16(v.w - __bfloat162float(hw));
            int o = (r * SA + c4 * 4) * 2;  // byte offset
            *(__nv_bfloat162*)(smem + SM_AH + o)     = __halves2bfloat162(hx, hy);
            *(__nv_bfloat162*)(smem + SM_AH + o + 4) = __halves2bfloat162(hz, hw);
            *(__nv_bfloat162*)(smem + SM_AL + o)     = __halves2bfloat162(lx, ly);
            *(__nv_bfloat162*)(smem + SM_AL + o + 4) = __halves2bfloat162(lz, lw);
        }
    };
    auto loadB = [&](int ch, int buf) {
        const int k0 = ch * 64;
        const uint32_t base = sbase + SM_B0 + buf * BSTAGE;
#pragma unroll
        for (int i = 0; i < 4; i++) {       // 2048 x 16B
            int idx = tid + i * 512;
            int r = idx >> 3, u = idx & 7;
            uint32_t d = base + (uint32_t)(r * SA + u * 8) * 2;
            CPA16(d, g_w1t_hi + r * 256 + k0 + u * 8);
            CPA16(d + BHALF, g_w1t_lo + r * 256 + k0 + u * 8);
        }
    };

    float acc[4][4][4];
#pragma unroll
    for (int i = 0; i < 4; i++)
#pragma unroll
        for (int j = 0; j < 4; j++)
#pragma unroll
            for (int r = 0; r < 4; r++) acc[i][j][r] = 0.0f;

    ldgA(0);
    loadB(0, 0); CPC();

    for (int ch = 0; ch < 4; ch++) {
        const int buf = ch & 1;
        stsA();                              // A(ch) regs -> smem (buffer free after last sync)
        if (ch < 3) { ldgA(ch + 1); loadB(ch + 1, buf ^ 1); CPC(); CPW(1); }
        else CPW(0);
        __syncthreads();

        const char* Ah = smem + SM_AH;
        const char* Al = smem + SM_AL;
        const char* Bh = smem + SM_B0 + buf * BSTAGE;
        const char* Bl = Bh + BHALF;

#pragma unroll
        for (int ks = 0; ks < 4; ks++) {
            const int kb = ks * 16;
            uint32_t bh[4][2], bl[4][2];
#pragma unroll
            for (int j = 0; j < 4; j++) {
                int n = wn + j * 8 + g;
                int o = (n * SA + kb + tg * 2) * 2;
                bh[j][0] = *(const uint32_t*)(Bh + o);
                bh[j][1] = *(const uint32_t*)(Bh + o + 16);
                bl[j][0] = *(const uint32_t*)(Bl + o);
                bl[j][1] = *(const uint32_t*)(Bl + o + 16);
            }
#pragma unroll
            for (int i = 0; i < 4; i++) {
                int m = wm + i * 16;
                int o0 = ((m + g) * SA + kb + tg * 2) * 2;
                int o1 = ((m + g + 8) * SA + kb + tg * 2) * 2;
                uint32_t ah[4], al[4];
                ah[0] = *(const uint32_t*)(Ah + o0);
                ah[1] = *(const uint32_t*)(Ah + o1);
                ah[2] = *(const uint32_t*)(Ah + o0 + 16);
                ah[3] = *(const uint32_t*)(Ah + o1 + 16);
                al[0] = *(const uint32_t*)(Al + o0);
                al[1] = *(const uint32_t*)(Al + o1);
                al[2] = *(const uint32_t*)(Al + o0 + 16);
                al[3] = *(const uint32_t*)(Al + o1 + 16);
#pragma unroll
                for (int j = 0; j < 4; j++) {
                    mma16816(acc[i][j], ah, bh[j]);
                    mma16816(acc[i][j], ah, bl[j]);
                    mma16816(acc[i][j], al, bh[j]);
                }
            }
        }
        __syncthreads();
    }

    // epilogue
#pragma unroll
    for (int j = 0; j < 4; j++) {
        int col = wn + j * 8 + tg * 2;
        float bx = __ldg(&bias[col]);
        float by = __ldg(&bias[col + 1]);
#pragma unroll
        for (int i = 0; i < 4; i++) {
            int r0 = rowBase + wm + i * 16 + g;
            if (r0 < N_NODES) {
                float2 v = make_float2(acc[i][j][0] + bx, acc[i][j][1] + by);
                *(float2*)(g_h1 + (size_t)r0 * 256 + col) = v;
            }
            int r1 = r0 + 8;
            if (r1 < N_NODES) {
                float2 v = make_float2(acc[i][j][2] + bx, acc[i][j][3] + by);
                *(float2*)(g_h1 + (size_t)r1 * 256 + col) = v;
            }
        }
    }
}

// ---------------- agg1: 2 warps per dst node, CSR gather, relu, 2x unrolled ----------------
__global__ __launch_bounds__(256) void k_agg1() {
    int wid = blockIdx.x * 8 + (threadIdx.x >> 5);
    int node = wid >> 1;
    if (node >= N_NODES) return;
    int half = wid & 1;
    int lane = threadIdx.x & 31;
    int fo = half * 32 + lane;

    float dv = g_dis[node];
    float self = dv * dv;
    float4 acc = ((const float4*)(g_h1 + (size_t)node * HID))[fo];
    acc.x *= self; acc.y *= self; acc.z *= self; acc.w *= self;

    int p = g_off[node], end = p + g_cnt[node];
    for (; p + 2 <= end; p += 2) {
        int s0 = __ldg(&g_ssrc[p]);
        int s1 = __ldg(&g_ssrc[p + 1]);
        float n0 = __ldg(&g_snorm[p]);
        float n1 = __ldg(&g_snorm[p + 1]);
        float4 v0 = ((const float4*)(g_h1 + (size_t)s0 * HID))[fo];
        float4 v1 = ((const float4*)(g_h1 + (size_t)s1 * HID))[fo];
        acc.x = fmaf(v0.x, n0, acc.x); acc.y = fmaf(v0.y, n0, acc.y);
        acc.z = fmaf(v0.z, n0, acc.z); acc.w = fmaf(v0.w, n0, acc.w);
        acc.x = fmaf(v1.x, n1, acc.x); acc.y = fmaf(v1.y, n1, acc.y);
        acc.z = fmaf(v1.z, n1, acc.z); acc.w = fmaf(v1.w, n1, acc.w);
    }
    if (p < end) {
        int s = __ldg(&g_ssrc[p]);
        float nm = __ldg(&g_snorm[p]);
        float4 v = ((const float4*)(g_h1 + (size_t)s * HID))[fo];
        acc.x = fmaf(v.x, nm, acc.x); acc.y = fmaf(v.y, nm, acc.y);
        acc.z = fmaf(v.z, nm, acc.z); acc.w = fmaf(v.w, nm, acc.w);
    }

    acc.x = fmaxf(acc.x, 0.f); acc.y = fmaxf(acc.y, 0.f);
    acc.z = fmaxf(acc.z, 0.f); acc.w = fmaxf(acc.w, 0.f);
    ((float4*)(g_a1 + (size_t)node * HID))[fo] = acc;
}

// ---------------- GEMM2: g_h2 = a1 @ W2 + b2 ----------------
__global__ __launch_bounds__(256) void k_gemm2(const float* __restrict__ W2,
                                               const float* __restrict__ b2) {
    __shared__ float sW[HID * NC];
    for (int i = threadIdx.x; i < HID * NC; i += 256) sW[i] = W2[i];
    __syncthreads();

    int row = blockIdx.x * 64 + (threadIdx.x >> 2);
    int cg = (threadIdx.x & 3) * 10;
    if (row >= N_NODES) return;

    float acc[10];
#pragma unroll
    for (int c = 0; c < 10; c++) acc[c] = b2[cg + c];

    const float4* a = (const float4*)(g_a1 + (size_t)row * HID);
    for (int k4 = 0; k4 < HID / 4; k4++) {
        float4 av = a[k4];
        float v[4] = {av.x, av.y, av.z, av.w};
#pragma unroll
        for (int kk = 0; kk < 4; kk++) {
            int k = k4 * 4 + kk;
#pragma unroll
            for (int c = 0; c < 10; c++)
                acc[c] = fmaf(v[kk], sW[k * NC + cg + c], acc[c]);
        }
    }
#pragma unroll
    for (int c = 0; c < 10; c++) g_h2[(size_t)row * NC + cg + c] = acc[c];
}

// ---------------- agg2 + log_softmax fused ----------------
__global__ __launch_bounds__(256) void k_agg2_lsm(float* __restrict__ out) {
    int node = blockIdx.x * 8 + (threadIdx.x >> 5);
    if (node >= N_NODES) return;
    int lane = threadIdx.x & 31;

    float dv = g_dis[node];
    float self = dv * dv;
    const float* hd = g_h2 + (size_t)node * NC;
    float a0 = hd[lane] * self;
    float a1 = (lane < 8) ? hd[lane + 32] * self : 0.f;

    int beg = g_off[node], end = beg + g_cnt[node];
    for (int p = beg; p < end; p++) {
        int s = __ldg(&g_ssrc[p]);
        float nm = __ldg(&g_snorm[p]);
        const float* hs = g_h2 + (size_t)s * NC;
        a0 = fmaf(__ldg(&hs[lane]), nm, a0);
        if (lane < 8) a1 = fmaf(__ldg(&hs[lane + 32]), nm, a1);
    }

    float m = (lane < 8) ? fmaxf(a0, a1) : a0;
#pragma unroll
    for (int o = 16; o >= 1; o >>= 1)
        m = fmaxf(m, __shfl_xor_sync(0xFFFFFFFFu, m, o));
    float s = __expf(a0 - m) + ((lane < 8) ? __expf(a1 - m) : 0.f);
#pragma unroll
    for (int o = 16; o >= 1; o >>= 1)
        s += __shfl_xor_sync(0xFFFFFFFFu, s, o);
    float ls = m + logf(s);

    float* op = out + (size_t)node * NC;
    op[lane] = a0 - ls;
    if (lane < 8) op[lane + 32] = a1 - ls;
}

// ---------------- launch (forked: preprocessing || gemm1 path) ----------------
extern "C" void kernel_launch(void* const* d_in, const int* in_sizes, int n_in,
                              void* d_out, int out_size) {
    const float* x  = (const float*)d_in[0];
    const int*   ei = (const int*)d_in[1];
    const float* ew = (const float*)d_in[2];
    const float* W1 = (const float*)d_in[3];
    const float* b1 = (const float*)d_in[4];
    const float* W2 = (const float*)d_in[5];
    const float* b2 = (const float*)d_in[6];
    float* out = (float*)d_out;

    const int* src = ei;
    const int* dst = ei + N_EDGES;

    cudaFuncSetAttribute(k_gemm1_mma, cudaFuncAttributeMaxDynamicSharedMemorySize, SM_G1);

    cudaStream_t s2;
    cudaStreamCreateWithFlags(&s2, cudaStreamNonBlocking);
    cudaEvent_t eF, eJ;
    cudaEventCreateWithFlags(&eF, cudaEventDisableTiming);
    cudaEventCreateWithFlags(&eJ, cudaEventDisableTiming);

    // fork: gemm1 path on s2 (independent of edge preprocessing)
    cudaEventRecord(eF, 0);
    cudaStreamWaitEvent(s2, eF, 0);
    k_w1t<<<256, 256, 0, s2>>>(W1);
    k_gemm1_mma<<<N_PAD / 128, 512, SM_G1, s2>>>(x, b1);
    cudaEventRecord(eJ, s2);

    // preprocessing on main stream
    k_init<<<(N_NODES + 255) / 256, 256>>>();
    k_cnt<<<(N_EDGES + 255) / 256, 256>>>(dst, ew);
    k_fin<<<(N_NODES + 255) / 256, 256>>>();
    k_fill<<<(N_EDGES + 255) / 256, 256>>>(src, dst, ew);

    // join, then dependent chain
    cudaStreamWaitEvent(0, eJ, 0);
    k_agg1<<<(2 * N_NODES + 7) / 8, 256>>>();
    k_gemm2<<<(N_NODES + 63) / 64, 256>>>(W2, b2);
    k_agg2_lsm<<<(N_NODES + 7) / 8, 256>>>(out);
}

// round 12
// speedup vs baseline: 2.1686x; 1.0368x over previous
#include <cuda_runtime.h>
#include <cuda_bf16.h>
#include <cuda_fp16.h>
#include <math.h>
#include <cstdint>

#define N_NODES 100000
#define N_EDGES 1600000
#define N_PAD 100096            // 782 * 128
#define F_IN 256
#define HID 256
#define NC 40

// ---------------- scratch (static device globals; no allocation) ----------------
__device__ float g_dis[N_NODES];
__device__ int   g_cnt[N_NODES];
__device__ int   g_off[N_NODES];
__device__ int   g_cur[N_NODES];
__device__ int   g_total;
__device__ int   g_ssrc[N_EDGES];
__device__ float g_snorm[N_EDGES];
__device__ float g_h1[(size_t)N_NODES * HID];
__device__ __half g_h1h[(size_t)N_NODES * HID];   // fp16 mirror for gathers
__device__ float g_a1[(size_t)N_NODES * HID];
__device__ float g_h2[(size_t)N_NODES * NC];
__device__ __nv_bfloat16 g_w1t_hi[256 * 256];   // W1^T [n][k]
__device__ __nv_bfloat16 g_w1t_lo[256 * 256];

__device__ __forceinline__ uint32_t smem_u32(const void* p) {
    uint32_t a;
    asm("{ .reg .u64 t; cvta.to.shared.u64 t, %1; cvt.u32.u64 %0, t; }" : "=r"(a) : "l"(p));
    return a;
}
#define CPA16(dst, src) asm volatile("cp.async.cg.shared.global [%0], [%1], 16;" :: "r"(dst), "l"(src))
#define CPC()  asm volatile("cp.async.commit_group;" ::: "memory")
#define CPW(n) asm volatile("cp.async.wait_group %0;" :: "n"(n) : "memory")

// ---------------- preprocessing ----------------
__global__ void k_init() {
    int i = blockIdx.x * blockDim.x + threadIdx.x;
    if (i < N_NODES) { g_dis[i] = 1.0f; g_cnt[i] = 0; g_cur[i] = 0; }
    if (i == 0) g_total = 0;
}

__global__ void k_cnt(const int* __restrict__ dst, const float* __restrict__ ew) {
    int e = blockIdx.x * blockDim.x + threadIdx.x;
    if (e < N_EDGES) {
        int d = dst[e];
        atomicAdd(&g_dis[d], ew[e]);
        atomicAdd(&g_cnt[d], 1);
    }
}

__global__ void k_fin() {
    int i = blockIdx.x * blockDim.x + threadIdx.x;
    if (i < N_NODES) {
        g_dis[i] = rsqrtf(g_dis[i]);
        g_off[i] = atomicAdd(&g_total, g_cnt[i]);
    }
}

__global__ void k_fill(const int* __restrict__ src, const int* __restrict__ dst,
                       const float* __restrict__ ew) {
    int e = blockIdx.x * blockDim.x + threadIdx.x;
    if (e >= N_EDGES) return;
    int d = dst[e];
    int s = src[e];
    int pos = g_off[d] + atomicAdd(&g_cur[d], 1);
    g_ssrc[pos] = s;
    g_snorm[pos] = g_dis[s] * ew[e] * g_dis[d];
}

// ---------------- W1 transpose + bf16 split ----------------
__global__ void k_w1t(const float* __restrict__ W1) {
    int t = blockIdx.x * blockDim.x + threadIdx.x;
    if (t >= 256 * 256) return;
    int n = t >> 8, k = t & 255;
    float w = W1[k * 256 + n];
    __nv_bfloat16 hi = __float2bfloat16(w);
    __nv_bfloat16 lo = __float2bfloat16(w - __bfloat162float(hi));
    g_w1t_hi[t] = hi;
    g_w1t_lo[t] = lo;
}

// ---------------- mma.sync m16n8k16 bf16 ----------------
__device__ __forceinline__ void mma16816(float* c, const uint32_t* a, const uint32_t* b) {
    asm volatile(
        "mma.sync.aligned.m16n8k16.row.col.f32.bf16.bf16.f32 "
        "{%0,%1,%2,%3}, {%4,%5,%6,%7}, {%8,%9}, {%0,%1,%2,%3};\n"
        : "+f"(c[0]), "+f"(c[1]), "+f"(c[2]), "+f"(c[3])
        : "r"(a[0]), "r"(a[1]), "r"(a[2]), "r"(a[3]), "r"(b[0]), "r"(b[1]));
}

// ---------------- GEMM1: 128x256 CTA, 512 threads ----------------
#define SA 72
#define SM_AH 0
#define SM_AL (128 * SA * 2)                // 18432
#define SM_B0 (2 * 128 * SA * 2)            // 36864
#define BHALF (256 * SA * 2)                // 36864
#define BSTAGE (2 * BHALF)                  // 73728
#define SM_G1 (SM_B0 + 2 * BSTAGE)          // 184320

__global__ __launch_bounds__(512) void k_gemm1_mma(const float* __restrict__ x,
                                                   const float* __restrict__ bias) {
    extern __shared__ char smem[];
    const uint32_t sbase = smem_u32(smem);
    const int tid = threadIdx.x;
    const int warp = tid >> 5;
    const int lane = tid & 31;
    const int g = lane >> 2;
    const int tg = lane & 3;
    const int wm = (warp >> 3) * 64;
    const int wn = (warp & 7) * 32;
    const int rowBase = blockIdx.x * 128;

    float4 vr[4];
    auto ldgA = [&](int ch) {
        const int k0 = ch * 64;
#pragma unroll
        for (int i = 0; i < 4; i++) {
            int idx = tid + i * 512;
            int r = idx >> 4, c4 = idx & 15;
            int gr = rowBase + r;
            vr[i] = (gr < N_NODES) ? *(const float4*)(x + (size_t)gr * 256 + k0 + c4 * 4)
                                   : make_float4(0.f, 0.f, 0.f, 0.f);
        }
    };
    auto stsA = [&]() {
#pragma unroll
        for (int i = 0; i < 4; i++) {
            int idx = tid + i * 512;
            int r = idx >> 4, c4 = idx & 15;
            float4 v = vr[i];
            __nv_bfloat16 hx = __float2bfloat16(v.x), hy = __float2bfloat16(v.y);
            __nv_bfloat16 hz = __float2bfloat16(v.z), hw = __float2bfloat16(v.w);
            __nv_bfloat16 lx = __float2bfloat16(v.x - __bfloat162float(hx));
            __nv_bfloat16 ly = __float2bfloat16(v.y - __bfloat162float(hy));
            __nv_bfloat16 lz = __float2bfloat16(v.z - __bfloat162float(hz));
            __nv_bfloat16 lw = __float2bfloat16(v.w - __bfloat162float(hw));
            int o = (r * SA + c4 * 4) * 2;
            *(__nv_bfloat162*)(smem + SM_AH + o)     = __halves2bfloat162(hx, hy);
            *(__nv_bfloat162*)(smem + SM_AH + o + 4) = __halves2bfloat162(hz, hw);
            *(__nv_bfloat162*)(smem + SM_AL + o)     = __halves2bfloat162(lx, ly);
            *(__nv_bfloat162*)(smem + SM_AL + o + 4) = __halves2bfloat162(lz, lw);
        }
    };
    auto loadB = [&](int ch, int buf) {
        const int k0 = ch * 64;
        const uint32_t base = sbase + SM_B0 + buf * BSTAGE;
#pragma unroll
        for (int i = 0; i < 4; i++) {
            int idx = tid + i * 512;
            int r = idx >> 3, u = idx & 7;
            uint32_t d = base + (uint32_t)(r * SA + u * 8) * 2;
            CPA16(d, g_w1t_hi + r * 256 + k0 + u * 8);
            CPA16(d + BHALF, g_w1t_lo + r * 256 + k0 + u * 8);
        }
    };

    float acc[4][4][4];
#pragma unroll
    for (int i = 0; i < 4; i++)
#pragma unroll
        for (int j = 0; j < 4; j++)
#pragma unroll
            for (int r = 0; r < 4; r++) acc[i][j][r] = 0.0f;

    ldgA(0);
    loadB(0, 0); CPC();

    for (int ch = 0; ch < 4; ch++) {
        const int buf = ch & 1;
        stsA();
        if (ch < 3) { ldgA(ch + 1); loadB(ch + 1, buf ^ 1); CPC(); CPW(1); }
        else CPW(0);
        __syncthreads();

        const char* Ah = smem + SM_AH;
        const char* Al = smem + SM_AL;
        const char* Bh = smem + SM_B0 + buf * BSTAGE;
        const char* Bl = Bh + BHALF;

#pragma unroll
        for (int ks = 0; ks < 4; ks++) {
            const int kb = ks * 16;
            uint32_t bh[4][2], bl[4][2];
#pragma unroll
            for (int j = 0; j < 4; j++) {
                int n = wn + j * 8 + g;
                int o = (n * SA + kb + tg * 2) * 2;
                bh[j][0] = *(const uint32_t*)(Bh + o);
                bh[j][1] = *(const uint32_t*)(Bh + o + 16);
                bl[j][0] = *(const uint32_t*)(Bl + o);
                bl[j][1] = *(const uint32_t*)(Bl + o + 16);
            }
#pragma unroll
            for (int i = 0; i < 4; i++) {
                int m = wm + i * 16;
                int o0 = ((m + g) * SA + kb + tg * 2) * 2;
                int o1 = ((m + g + 8) * SA + kb + tg * 2) * 2;
                uint32_t ah[4], al[4];
                ah[0] = *(const uint32_t*)(Ah + o0);
                ah[1] = *(const uint32_t*)(Ah + o1);
                ah[2] = *(const uint32_t*)(Ah + o0 + 16);
                ah[3] = *(const uint32_t*)(Ah + o1 + 16);
                al[0] = *(const uint32_t*)(Al + o0);
                al[1] = *(const uint32_t*)(Al + o1);
                al[2] = *(const uint32_t*)(Al + o0 + 16);
                al[3] = *(const uint32_t*)(Al + o1 + 16);
#pragma unroll
                for (int j = 0; j < 4; j++) {
                    mma16816(acc[i][j], ah, bh[j]);
                    mma16816(acc[i][j], ah, bl[j]);
                    mma16816(acc[i][j], al, bh[j]);
                }
            }
        }
        __syncthreads();
    }

    // epilogue: write fp32 h1 and fp16 mirror
#pragma unroll
    for (int j = 0; j < 4; j++) {
        int col = wn + j * 8 + tg * 2;
        float bx = __ldg(&bias[col]);
        float by = __ldg(&bias[col + 1]);
#pragma unroll
        for (int i = 0; i < 4; i++) {
            int r0 = rowBase + wm + i * 16 + g;
            if (r0 < N_NODES) {
                float vx = acc[i][j][0] + bx, vy = acc[i][j][1] + by;
                *(float2*)(g_h1 + (size_t)r0 * 256 + col) = make_float2(vx, vy);
                *(__half2*)(g_h1h + (size_t)r0 * 256 + col) = __floats2half2_rn(vx, vy);
            }
            int r1 = r0 + 8;
            if (r1 < N_NODES) {
                float vx = acc[i][j][2] + bx, vy = acc[i][j][3] + by;
                *(float2*)(g_h1 + (size_t)r1 * 256 + col) = make_float2(vx, vy);
                *(__half2*)(g_h1h + (size_t)r1 * 256 + col) = __floats2half2_rn(vx, vy);
            }
        }
    }
}

// ---------------- agg1: 2 warps per node; fp32 self + fp16 edge gathers ----------------
__global__ __launch_bounds__(256) void k_agg1() {
    int wid = blockIdx.x * 8 + (threadIdx.x >> 5);
    int node = wid >> 1;
    if (node >= N_NODES) return;
    int half = wid & 1;
    int lane = threadIdx.x & 31;
    int fo = half * 32 + lane;          // float4 / uint2 index (4 feats)

    float dv = g_dis[node];
    float self = dv * dv;
    float4 acc = ((const float4*)(g_h1 + (size_t)node * HID))[fo];
    acc.x *= self; acc.y *= self; acc.z *= self; acc.w *= self;

    const uint2* hh = (const uint2*)g_h1h;
    int p = g_off[node], end = p + g_cnt[node];
    for (; p + 2 <= end; p += 2) {
        int s0 = __ldg(&g_ssrc[p]);
        int s1 = __ldg(&g_ssrc[p + 1]);
        float n0 = __ldg(&g_snorm[p]);
        float n1 = __ldg(&g_snorm[p + 1]);
        uint2 u0 = __ldg(&hh[(size_t)s0 * 64 + fo]);
        uint2 u1 = __ldg(&hh[(size_t)s1 * 64 + fo]);
        float2 a0 = __half22float2(*(__half2*)&u0.x);
        float2 b0 = __half22float2(*(__half2*)&u0.y);
        float2 a1f = __half22float2(*(__half2*)&u1.x);
        float2 b1f = __half22float2(*(__half2*)&u1.y);
        acc.x = fmaf(a0.x, n0, acc.x); acc.y = fmaf(a0.y, n0, acc.y);
        acc.z = fmaf(b0.x, n0, acc.z); acc.w = fmaf(b0.y, n0, acc.w);
        acc.x = fmaf(a1f.x, n1, acc.x); acc.y = fmaf(a1f.y, n1, acc.y);
        acc.z = fmaf(b1f.x, n1, acc.z); acc.w = fmaf(b1f.y, n1, acc.w);
    }
    if (p < end) {
        int s = __ldg(&g_ssrc[p]);
        float nm = __ldg(&g_snorm[p]);
        uint2 u = __ldg(&hh[(size_t)s * 64 + fo]);
        float2 a = __half22float2(*(__half2*)&u.x);
        float2 b = __half22float2(*(__half2*)&u.y);
        acc.x = fmaf(a.x, nm, acc.x); acc.y = fmaf(a.y, nm, acc.y);
        acc.z = fmaf(b.x, nm, acc.z); acc.w = fmaf(b.y, nm, acc.w);
    }

    acc.x = fmaxf(acc.x, 0.f); acc.y = fmaxf(acc.y, 0.f);
    acc.z = fmaxf(acc.z, 0.f); acc.w = fmaxf(acc.w, 0.f);
    ((float4*)(g_a1 + (size_t)node * HID))[fo] = acc;
}

// ---------------- GEMM2: g_h2 = a1 @ W2 + b2 ----------------
__global__ __launch_bounds__(256) void k_gemm2(const float* __restrict__ W2,
                                               const float* __restrict__ b2) {
    __shared__ float sW[HID * NC];
    for (int i = threadIdx.x; i < HID * NC; i += 256) sW[i] = W2[i];
    __syncthreads();

    int row = blockIdx.x * 64 + (threadIdx.x >> 2);
    int cg = (threadIdx.x & 3) * 10;
    if (row >= N_NODES) return;

    float acc[10];
#pragma unroll
    for (int c = 0; c < 10; c++) acc[c] = b2[cg + c];

    const float4* a = (const float4*)(g_a1 + (size_t)row * HID);
    for (int k4 = 0; k4 < HID / 4; k4++) {
        float4 av = a[k4];
        float v[4] = {av.x, av.y, av.z, av.w};
#pragma unroll
        for (int kk = 0; kk < 4; kk++) {
            int k = k4 * 4 + kk;
#pragma unroll
            for (int c = 0; c < 10; c++)
                acc[c] = fmaf(v[kk], sW[k * NC + cg + c], acc[c]);
        }
    }
#pragma unroll
    for (int c = 0; c < 10; c++) g_h2[(size_t)row * NC + cg + c] = acc[c];
}

// ---------------- agg2 + log_softmax fused ----------------
__global__ __launch_bounds__(256) void k_agg2_lsm(float* __restrict__ out) {
    int node = blockIdx.x * 8 + (threadIdx.x >> 5);
    if (node >= N_NODES) return;
    int lane = threadIdx.x & 31;

    float dv = g_dis[node];
    float self = dv * dv;
    const float* hd = g_h2 + (size_t)node * NC;
    float a0 = hd[lane] * self;
    float a1 = (lane < 8) ? hd[lane + 32] * self : 0.f;

    int beg = g_off[node], end = beg + g_cnt[node];
    for (int p = beg; p < end; p++) {
        int s = __ldg(&g_ssrc[p]);
        float nm = __ldg(&g_snorm[p]);
        const float* hs = g_h2 + (size_t)s * NC;
        a0 = fmaf(__ldg(&hs[lane]), nm, a0);
        if (lane < 8) a1 = fmaf(__ldg(&hs[lane + 32]), nm, a1);
    }

    float m = (lane < 8) ? fmaxf(a0, a1) : a0;
#pragma unroll
    for (int o = 16; o >= 1; o >>= 1)
        m = fmaxf(m, __shfl_xor_sync(0xFFFFFFFFu, m, o));
    float s = __expf(a0 - m) + ((lane < 8) ? __expf(a1 - m) : 0.f);
#pragma unroll
    for (int o = 16; o >= 1; o >>= 1)
        s += __shfl_xor_sync(0xFFFFFFFFu, s, o);
    float ls = m + logf(s);

    float* op = out + (size_t)node * NC;
    op[lane] = a0 - ls;
    if (lane < 8) op[lane + 32] = a1 - ls;
}

// ---------------- launch (forked: preprocessing || gemm1 path) ----------------
extern "C" void kernel_launch(void* const* d_in, const int* in_sizes, int n_in,
                              void* d_out, int out_size) {
    const float* x  = (const float*)d_in[0];
    const int*   ei = (const int*)d_in[1];
    const float* ew = (const float*)d_in[2];
    const float* W1 = (const float*)d_in[3];
    const float* b1 = (const float*)d_in[4];
    const float* W2 = (const float*)d_in[5];
    const float* b2 = (const float*)d_in[6];
    float* out = (float*)d_out;

    const int* src = ei;
    const int* dst = ei + N_EDGES;

    cudaFuncSetAttribute(k_gemm1_mma, cudaFuncAttributeMaxDynamicSharedMemorySize, SM_G1);

    cudaStream_t s2;
    cudaStreamCreateWithFlags(&s2, cudaStreamNonBlocking);
    cudaEvent_t eF, eJ;
    cudaEventCreateWithFlags(&eF, cudaEventDisableTiming);
    cudaEventCreateWithFlags(&eJ, cudaEventDisableTiming);

    // fork: gemm1 path on s2 (independent of edge preprocessing)
    cudaEventRecord(eF, 0);
    cudaStreamWaitEvent(s2, eF, 0);
    k_w1t<<<256, 256, 0, s2>>>(W1);
    k_gemm1_mma<<<N_PAD / 128, 512, SM_G1, s2>>>(x, b1);
    cudaEventRecord(eJ, s2);

    // preprocessing on main stream
    k_init<<<(N_NODES + 255) / 256, 256>>>();
    k_cnt<<<(N_EDGES + 255) / 256, 256>>>(dst, ew);
    k_fin<<<(N_NODES + 255) / 256, 256>>>();
    k_fill<<<(N_EDGES + 255) / 256, 256>>>(src, dst, ew);

    // join, then dependent chain
    cudaStreamWaitEvent(0, eJ, 0);
    k_agg1<<<(2 * N_NODES + 7) / 8, 256>>>();
    k_gemm2<<<(N_NODES + 63) / 64, 256>>>(W2, b2);
    k_agg2_lsm<<<(N_NODES + 7) / 8, 256>>>(out);
}